// round 1
// baseline (speedup 1.0000x reference)
#include <cuda_runtime.h>
#include <math.h>

// ---------------- problem constants ----------------
#define Bsz   8192
#define DIN   2048
#define H0    1024
#define H1    512
#define LAT   128
#define NC    8

// GEMM tile config
#define BM 128
#define BN 128
#define BK 8
#define TM 8
#define TN 8
#define NTHREADS 256
#define MAX_TILES 80

// ---------------- device scratch (no allocs allowed) ----------------
__device__ float g_xp  [Bsz * DIN];   // permuted x
__device__ float g_epsp[Bsz * LAT];   // permuted eps
__device__ float g_h0  [Bsz * H0];
__device__ float g_h1  [Bsz * H1];
__device__ float g_mu  [Bsz * LAT];
__device__ float g_lv  [Bsz * LAT];
__device__ float g_zp  [Bsz * LAT];
__device__ float g_d1  [Bsz * H1];
__device__ float g_d2  [Bsz * H0];

__device__ int g_cnt[NC];
__device__ int g_fill[NC];
__device__ int g_segoff[NC + 1];
__device__ int g_perm[Bsz];           // perm[i] = original row of permuted row i

struct Tile { int row_start; int row_end; int cluster; };
__device__ Tile g_tiles[MAX_TILES];
__device__ int  g_ntiles;

// ---------------- setup kernels ----------------
__global__ void zero_k() {
    int i = threadIdx.x;
    if (i < NC) { g_cnt[i] = 0; g_fill[i] = 0; }
}

__global__ void hist_k(const int* __restrict__ labels) {
    int i = blockIdx.x * blockDim.x + threadIdx.x;
    if (i < Bsz) atomicAdd(&g_cnt[labels[i]], 1);
}

__global__ void build_k() {
    // single thread: prefix sum + tile table
    int off = 0;
    for (int c = 0; c < NC; c++) { g_segoff[c] = off; off += g_cnt[c]; }
    g_segoff[NC] = off;   // == Bsz
    int t = 0;
    for (int c = 0; c < NC; c++) {
        int s = g_segoff[c], e = g_segoff[c + 1];
        for (int r = s; r < e; r += BM) {
            g_tiles[t].row_start = r;
            g_tiles[t].row_end   = min(r + BM, e);
            g_tiles[t].cluster   = c;
            t++;
        }
    }
    g_ntiles = t;
}

__global__ void scatter_perm_k(const int* __restrict__ labels) {
    int i = blockIdx.x * blockDim.x + threadIdx.x;
    if (i < Bsz) {
        int c = labels[i];
        int pos = g_segoff[c] + atomicAdd(&g_fill[c], 1);
        g_perm[pos] = i;
    }
}

// gather x and eps rows into permuted order
__global__ void gather_k(const float* __restrict__ x, const float* __restrict__ eps) {
    int r = blockIdx.x;
    int src = g_perm[r];
    const float4* xs = reinterpret_cast<const float4*>(x + (size_t)src * DIN);
    float4*       xd = reinterpret_cast<float4*>(g_xp + (size_t)r * DIN);
    #pragma unroll
    for (int j = threadIdx.x; j < DIN / 4; j += NTHREADS) xd[j] = xs[j];
    if (threadIdx.x < LAT / 4) {
        reinterpret_cast<float4*>(g_epsp + r * LAT)[threadIdx.x] =
            reinterpret_cast<const float4*>(eps + src * LAT)[threadIdx.x];
    }
}

// ---------------- main tiled GEMM ----------------
// C[M,N] = act(A[M,K] @ W[K,N] + bias), optional cluster grouping & row scatter.
template<bool GROUPED, bool RELU, bool SCATTER>
__global__ __launch_bounds__(NTHREADS)
void gemm_k(const float* __restrict__ A, int lda,
            const float* __restrict__ W, int wstride,   // elements per cluster matrix
            const float* __restrict__ bias, int bstride,
            float* __restrict__ out, int ldo,
            int N, int K, int Mtotal,
            const int* __restrict__ perm)
{
    int row0, row_end, c;
    if (GROUPED) {
        int t = blockIdx.y;
        if (t >= g_ntiles) return;
        Tile tl = g_tiles[t];
        row0 = tl.row_start; row_end = tl.row_end; c = tl.cluster;
    } else {
        row0 = blockIdx.y * BM; row_end = row0 + BM; c = 0;
    }
    const float* Wc = W + (size_t)c * wstride;
    const float* bc = bias + c * bstride;
    int col0 = blockIdx.x * BN;

    __shared__ float As[2][BK][BM];
    __shared__ float Bs[2][BK][BN];

    int tid = threadIdx.x;
    int tx = tid & 15, ty = tid >> 4;

    // load mapping
    int a_row = tid >> 1;          // 0..127
    int a_k   = (tid & 1) * 4;     // 0 or 4
    int b_row = tid >> 5;          // 0..7
    int b_col = (tid & 31) * 4;    // 0..124

    float acc[TM][TN];
    #pragma unroll
    for (int i = 0; i < TM; i++)
        #pragma unroll
        for (int j = 0; j < TN; j++) acc[i][j] = 0.f;

    // prefetch k0 = 0
    float4 av, bv;
    {
        int grow = row0 + a_row;
        if (!GROUPED || grow < row_end)
            av = *reinterpret_cast<const float4*>(A + (size_t)grow * lda + a_k);
        else
            av = make_float4(0.f, 0.f, 0.f, 0.f);
        bv = *reinterpret_cast<const float4*>(Wc + (size_t)b_row * N + col0 + b_col);
    }
    As[0][a_k + 0][a_row] = av.x;
    As[0][a_k + 1][a_row] = av.y;
    As[0][a_k + 2][a_row] = av.z;
    As[0][a_k + 3][a_row] = av.w;
    *reinterpret_cast<float4*>(&Bs[0][b_row][b_col]) = bv;
    __syncthreads();

    int p = 0;
    for (int k0 = 0; k0 < K; k0 += BK) {
        bool has_next = (k0 + BK) < K;
        if (has_next) {
            int kn = k0 + BK;
            int grow = row0 + a_row;
            if (!GROUPED || grow < row_end)
                av = *reinterpret_cast<const float4*>(A + (size_t)grow * lda + kn + a_k);
            else
                av = make_float4(0.f, 0.f, 0.f, 0.f);
            bv = *reinterpret_cast<const float4*>(Wc + (size_t)(kn + b_row) * N + col0 + b_col);
        }
        // compute on buffer p
        #pragma unroll
        for (int kk = 0; kk < BK; kk++) {
            float a[TM], b[TN];
            float4 a0 = *reinterpret_cast<const float4*>(&As[p][kk][ty * TM]);
            float4 a1 = *reinterpret_cast<const float4*>(&As[p][kk][ty * TM + 4]);
            a[0]=a0.x; a[1]=a0.y; a[2]=a0.z; a[3]=a0.w;
            a[4]=a1.x; a[5]=a1.y; a[6]=a1.z; a[7]=a1.w;
            float4 b0 = *reinterpret_cast<const float4*>(&Bs[p][kk][tx * TN]);
            float4 b1 = *reinterpret_cast<const float4*>(&Bs[p][kk][tx * TN + 4]);
            b[0]=b0.x; b[1]=b0.y; b[2]=b0.z; b[3]=b0.w;
            b[4]=b1.x; b[5]=b1.y; b[6]=b1.z; b[7]=b1.w;
            #pragma unroll
            for (int i = 0; i < TM; i++)
                #pragma unroll
                for (int j = 0; j < TN; j++)
                    acc[i][j] = fmaf(a[i], b[j], acc[i][j]);
        }
        if (has_next) {
            int q = p ^ 1;
            As[q][a_k + 0][a_row] = av.x;
            As[q][a_k + 1][a_row] = av.y;
            As[q][a_k + 2][a_row] = av.z;
            As[q][a_k + 3][a_row] = av.w;
            *reinterpret_cast<float4*>(&Bs[q][b_row][b_col]) = bv;
            __syncthreads();
            p = q;
        }
    }

    // epilogue
    #pragma unroll
    for (int i = 0; i < TM; i++) {
        int r = row0 + ty * TM + i;
        if (GROUPED && r >= row_end) break;
        size_t orow = SCATTER ? (size_t)perm[r] : (size_t)r;
        float* op = out + orow * ldo + col0;
        #pragma unroll
        for (int j = 0; j < TN; j++) {
            float v = acc[i][j] + bc[col0 * 0 + tx * TN + j + 0] ;
            // note: bias index relative to col0 handled below
            (void)v;
        }
        // correct bias indexing (bias is over full N; our tile starts at col0)
        #pragma unroll
        for (int j = 0; j < TN; j++) {
            float v = acc[i][j] + bc[col0 + tx * TN + j];
            if (RELU) v = fmaxf(v, 0.f);
            op[tx * TN + j] = v;
        }
    }
}

// ---------------- reparameterize + scatter mu/logvar ----------------
__global__ void latent_k(float* __restrict__ out) {
    int idx = blockIdx.x * blockDim.x + threadIdx.x;   // over Bsz*LAT
    if (idx >= Bsz * LAT) return;
    int r = idx >> 7;        // LAT = 128
    int j = idx & 127;
    float mu = g_mu[idx];
    float lv = g_lv[idx];
    float z  = mu + g_epsp[idx] * expf(0.5f * lv);
    g_zp[idx] = z;
    int orig = g_perm[r];
    out[(size_t)Bsz * DIN + (size_t)orig * LAT + j] = mu;
    out[(size_t)Bsz * DIN + (size_t)Bsz * LAT + (size_t)orig * LAT + j] = lv;
}

// ---------------- launcher ----------------
extern "C" void kernel_launch(void* const* d_in, const int* in_sizes, int n_in,
                              void* d_out, int out_size)
{
    const float* x        = (const float*)d_in[0];
    const int*   labels   = (const int*)  d_in[1];
    const float* eps      = (const float*)d_in[2];
    const float* W_enc0   = (const float*)d_in[3];
    const float* b_enc0   = (const float*)d_in[4];
    const float* W_enc1   = (const float*)d_in[5];
    const float* b_enc1   = (const float*)d_in[6];
    const float* W_mu     = (const float*)d_in[7];
    const float* b_mu     = (const float*)d_in[8];
    const float* W_logvar = (const float*)d_in[9];
    const float* b_logvar = (const float*)d_in[10];
    const float* W_dec0   = (const float*)d_in[11];
    const float* b_dec0   = (const float*)d_in[12];
    const float* W_dec1   = (const float*)d_in[13];
    const float* b_dec1   = (const float*)d_in[14];
    const float* W_out    = (const float*)d_in[15];
    const float* b_out    = (const float*)d_in[16];
    float* out = (float*)d_out;

    // device scratch pointers
    float *xp, *epsp, *h0, *h1, *mu, *lv, *zp, *d1, *d2;
    int *perm;
    cudaGetSymbolAddress((void**)&xp,   g_xp);
    cudaGetSymbolAddress((void**)&epsp, g_epsp);
    cudaGetSymbolAddress((void**)&h0,   g_h0);
    cudaGetSymbolAddress((void**)&h1,   g_h1);
    cudaGetSymbolAddress((void**)&mu,   g_mu);
    cudaGetSymbolAddress((void**)&lv,   g_lv);
    cudaGetSymbolAddress((void**)&zp,   g_zp);
    cudaGetSymbolAddress((void**)&d1,   g_d1);
    cudaGetSymbolAddress((void**)&d2,   g_d2);
    cudaGetSymbolAddress((void**)&perm, g_perm);

    // 1. routing setup
    zero_k<<<1, 32>>>();
    hist_k<<<(Bsz + 255) / 256, 256>>>(labels);
    build_k<<<1, 1>>>();
    scatter_perm_k<<<(Bsz + 255) / 256, 256>>>(labels);
    gather_k<<<Bsz, NTHREADS>>>(x, eps);

    // 2. encoder layer 0 (grouped): h0 = relu(xp @ W_enc0[c] + b_enc0[c])
    gemm_k<true, true, false><<<dim3(H0 / BN, MAX_TILES - 8), NTHREADS>>>(
        xp, DIN, W_enc0, DIN * H0, b_enc0, H0, h0, H0, H0, DIN, Bsz, perm);

    // 3. encoder layer 1 (shared): h1 = relu(h0 @ W_enc1 + b_enc1)
    gemm_k<false, true, false><<<dim3(H1 / BN, Bsz / BM), NTHREADS>>>(
        h0, H0, W_enc1, 0, b_enc1, 0, h1, H1, H1, H0, Bsz, perm);

    // 4. latent heads
    gemm_k<false, false, false><<<dim3(LAT / BN, Bsz / BM), NTHREADS>>>(
        h1, H1, W_mu, 0, b_mu, 0, mu, LAT, LAT, H1, Bsz, perm);
    gemm_k<false, false, false><<<dim3(LAT / BN, Bsz / BM), NTHREADS>>>(
        h1, H1, W_logvar, 0, b_logvar, 0, lv, LAT, LAT, H1, Bsz, perm);

    // 5. reparameterize + scatter mu/logvar to output
    latent_k<<<(Bsz * LAT + 255) / 256, 256>>>(out);

    // 6. decoder layer 0 (shared): d1 = relu(zp @ W_dec0 + b_dec0)
    gemm_k<false, true, false><<<dim3(H1 / BN, Bsz / BM), NTHREADS>>>(
        zp, LAT, W_dec0, 0, b_dec0, 0, d1, H1, H1, LAT, Bsz, perm);

    // 7. decoder layer 1 (grouped): d2 = relu(d1 @ W_dec1[c] + b_dec1[c])
    gemm_k<true, true, false><<<dim3(H0 / BN, MAX_TILES - 8), NTHREADS>>>(
        d1, H1, W_dec1, H1 * H0, b_dec1, H0, d2, H0, H0, H1, Bsz, perm);

    // 8. output layer (shared, scatter rows): recon = d2 @ W_out + b_out
    gemm_k<false, false, true><<<dim3(DIN / BN, Bsz / BM), NTHREADS>>>(
        d2, H0, W_out, 0, b_out, 0, out, DIN, DIN, H0, Bsz, perm);

    (void)in_sizes; (void)n_in; (void)out_size;
}

// round 4
// speedup vs baseline: 2.4141x; 2.4141x over previous
#include <cuda_runtime.h>
#include <cuda_bf16.h>
#include <cstdint>
#include <math.h>

// ---------------- problem constants ----------------
#define Bsz   8192
#define DIN   2048
#define H0    1024
#define H1    512
#define LAT   128
#define NC    8

#define BM 128
#define BN 128
#define KC 32
#define NTHR 256
#define MAX_TILES 80

// smem: 4 tiles per stage (Ahi, Alo, Bhi, Blo), each 128 rows x 80B (64B data + 16B pad)
#define T_SZ   (128 * 80)          // 10240
#define STAGE  (4 * T_SZ)          // 40960
#define SMEM_BYTES (2 * STAGE)     // 81920

// ---------------- device scratch ----------------
__device__ __align__(16) __nv_bfloat16 g_xhi[Bsz * DIN];
__device__ __align__(16) __nv_bfloat16 g_xlo[Bsz * DIN];
__device__ __align__(16) float         g_epsp[Bsz * LAT];
__device__ __align__(16) __nv_bfloat16 g_h0hi[Bsz * H0];
__device__ __align__(16) __nv_bfloat16 g_h0lo[Bsz * H0];
__device__ __align__(16) __nv_bfloat16 g_h1hi[Bsz * H1];
__device__ __align__(16) __nv_bfloat16 g_h1lo[Bsz * H1];
__device__ __align__(16) float         g_hd[Bsz * 256];     // mu|logvar raw (permuted rows)
__device__ __align__(16) __nv_bfloat16 g_zhi[Bsz * LAT];
__device__ __align__(16) __nv_bfloat16 g_zlo[Bsz * LAT];
__device__ __align__(16) __nv_bfloat16 g_d1hi[Bsz * H1];
__device__ __align__(16) __nv_bfloat16 g_d1lo[Bsz * H1];
__device__ __align__(16) __nv_bfloat16 g_d2hi[Bsz * H0];
__device__ __align__(16) __nv_bfloat16 g_d2lo[Bsz * H0];

// transposed split weights [N, K] per cluster
__device__ __align__(16) __nv_bfloat16 g_we0h[NC * DIN * H0];
__device__ __align__(16) __nv_bfloat16 g_we0l[NC * DIN * H0];
__device__ __align__(16) __nv_bfloat16 g_we1h[H0 * H1];
__device__ __align__(16) __nv_bfloat16 g_we1l[H0 * H1];
__device__ __align__(16) __nv_bfloat16 g_whdh[256 * H1];    // [mu;logvar] concat rows
__device__ __align__(16) __nv_bfloat16 g_whdl[256 * H1];
__device__ __align__(16) __nv_bfloat16 g_wd0h[H1 * LAT];
__device__ __align__(16) __nv_bfloat16 g_wd0l[H1 * LAT];
__device__ __align__(16) __nv_bfloat16 g_wd1h[NC * H1 * H0];
__device__ __align__(16) __nv_bfloat16 g_wd1l[NC * H1 * H0];
__device__ __align__(16) __nv_bfloat16 g_woh[DIN * H0];
__device__ __align__(16) __nv_bfloat16 g_wol[DIN * H0];

__device__ int g_cnt[NC];
__device__ int g_fill[NC];
__device__ int g_segoff[NC + 1];
__device__ int g_perm[Bsz];

struct Tile { int row_start; int row_end; int cluster; };
__device__ Tile g_tiles[MAX_TILES];
__device__ int  g_ntiles;

// ---------------- helpers (sm_80+ features only; no arch-specific 'a' instrs) ----
__device__ __forceinline__ uint32_t smem_u32(const void* p) {
    return (uint32_t)__cvta_generic_to_shared(p);
}
__device__ __forceinline__ void cp16(uint32_t saddr, const void* gptr) {
    asm volatile("cp.async.cg.shared.global [%0], [%1], 16;"
                 :: "r"(saddr), "l"(__cvta_generic_to_global(gptr)) : "memory");
}
__device__ __forceinline__ void cp_commit() {
    asm volatile("cp.async.commit_group;" ::: "memory");
}
template<int N> __device__ __forceinline__ void cp_wait() {
    asm volatile("cp.async.wait_group %0;" :: "n"(N) : "memory");
}
__device__ __forceinline__ void ldsm4(uint32_t a, uint32_t* r) {
    asm volatile("ldmatrix.sync.aligned.m8n8.x4.shared.b16 {%0,%1,%2,%3}, [%4];"
                 : "=r"(r[0]), "=r"(r[1]), "=r"(r[2]), "=r"(r[3]) : "r"(a));
}
__device__ __forceinline__ void mma16816(float* c, const uint32_t* a, const uint32_t* b) {
    asm volatile("mma.sync.aligned.m16n8k16.row.col.f32.bf16.bf16.f32 "
                 "{%0,%1,%2,%3}, {%4,%5,%6,%7}, {%8,%9}, {%0,%1,%2,%3};"
                 : "+f"(c[0]), "+f"(c[1]), "+f"(c[2]), "+f"(c[3])
                 : "r"(a[0]), "r"(a[1]), "r"(a[2]), "r"(a[3]), "r"(b[0]), "r"(b[1]));
}
__device__ __forceinline__ void split2(float v, __nv_bfloat16& h, __nv_bfloat16& l) {
    h = __float2bfloat16(v);
    l = __float2bfloat16(v - __bfloat162float(h));
}

// ---------------- setup kernels ----------------
__global__ void zero_k() {
    int i = threadIdx.x;
    if (i < NC) { g_cnt[i] = 0; g_fill[i] = 0; }
}
__global__ void hist_k(const int* __restrict__ labels) {
    int i = blockIdx.x * blockDim.x + threadIdx.x;
    if (i < Bsz) atomicAdd(&g_cnt[labels[i]], 1);
}
__global__ void build_k() {
    int off = 0;
    for (int c = 0; c < NC; c++) { g_segoff[c] = off; off += g_cnt[c]; }
    g_segoff[NC] = off;
    int t = 0;
    for (int c = 0; c < NC; c++) {
        int s = g_segoff[c], e = g_segoff[c + 1];
        for (int r = s; r < e; r += BM) {
            g_tiles[t].row_start = r;
            g_tiles[t].row_end   = min(r + BM, e);
            g_tiles[t].cluster   = c;
            t++;
        }
    }
    g_ntiles = t;
}
__global__ void scatter_perm_k(const int* __restrict__ labels) {
    int i = blockIdx.x * blockDim.x + threadIdx.x;
    if (i < Bsz) {
        int c = labels[i];
        int pos = g_segoff[c] + atomicAdd(&g_fill[c], 1);
        g_perm[pos] = i;
    }
}

// gather x rows to permuted order + split into bf16 hi/lo; gather eps
__global__ void gatherconv_k(const float* __restrict__ x, const float* __restrict__ eps) {
    int r = blockIdx.x;
    int src = g_perm[r];
    const float4* xs = reinterpret_cast<const float4*>(x + (size_t)src * DIN);
    size_t dbase = (size_t)r * DIN;
    for (int j = threadIdx.x; j < DIN / 4; j += NTHR) {
        float4 v = xs[j];
        __nv_bfloat16 h0, h1, h2, h3, l0, l1, l2, l3;
        split2(v.x, h0, l0); split2(v.y, h1, l1);
        split2(v.z, h2, l2); split2(v.w, h3, l3);
        __nv_bfloat162* dh = reinterpret_cast<__nv_bfloat162*>(g_xhi + dbase + 4 * (size_t)j);
        __nv_bfloat162* dl = reinterpret_cast<__nv_bfloat162*>(g_xlo + dbase + 4 * (size_t)j);
        dh[0] = __nv_bfloat162(h0, h1); dh[1] = __nv_bfloat162(h2, h3);
        dl[0] = __nv_bfloat162(l0, l1); dl[1] = __nv_bfloat162(l2, l3);
    }
    if (threadIdx.x < LAT / 4) {
        reinterpret_cast<float4*>(g_epsp + (size_t)r * LAT)[threadIdx.x] =
            reinterpret_cast<const float4*>(eps + (size_t)src * LAT)[threadIdx.x];
    }
}

// transpose + split: W [K,N] fp32 -> Wt_hi/lo [N,K] bf16 (C matrices via blockIdx.z)
__global__ void tsplit_k(const float* __restrict__ W,
                         __nv_bfloat16* __restrict__ hi, __nv_bfloat16* __restrict__ lo,
                         int K, int N) {
    __shared__ float t[32][33];
    int c = blockIdx.z;
    const float* Wc = W + (size_t)c * K * N;
    __nv_bfloat16* hic = hi + (size_t)c * K * N;
    __nv_bfloat16* loc = lo + (size_t)c * K * N;
    int n0 = blockIdx.x * 32, k0 = blockIdx.y * 32;
    int tx = threadIdx.x;
    for (int i = threadIdx.y; i < 32; i += 8)
        t[i][tx] = Wc[(size_t)(k0 + i) * N + n0 + tx];
    __syncthreads();
    for (int i = threadIdx.y; i < 32; i += 8) {
        float v = t[tx][i];   // = W[k0+tx][n0+i]
        __nv_bfloat16 h, l; split2(v, h, l);
        size_t o = (size_t)(n0 + i) * K + k0 + tx;
        hic[o] = h; loc[o] = l;
    }
}

// ---------------- HMMA split-bf16 GEMM (mma.sync m16n8k16) ----------------
// C[BM,BN] = A[M,K] @ W[K,N] via Wt[N,K]; 3 mma terms (hh, hl, lh), fp32 reg accum.
// EPI: 0 = relu + split store to Ohi/Olo; 1 = raw fp32 to g_hd (heads); 2 = +bias, scatter fp32 to out
template<int EPI, bool GROUPED>
__global__ __launch_bounds__(NTHR)
void hmma_gemm_k(const __nv_bfloat16* __restrict__ Ahi, const __nv_bfloat16* __restrict__ Alo, int lda,
                 const __nv_bfloat16* __restrict__ Whi, const __nv_bfloat16* __restrict__ Wlo, size_t wstride,
                 const float* __restrict__ bias, int bstride,
                 int N, int K,
                 __nv_bfloat16* __restrict__ Ohi, __nv_bfloat16* __restrict__ Olo, int ldo,
                 float* __restrict__ out)
{
    int row0, row_end, c;
    if (GROUPED) {
        int t = blockIdx.y;
        if (t >= g_ntiles) return;
        Tile tl = g_tiles[t];
        row0 = tl.row_start; row_end = tl.row_end; c = tl.cluster;
    } else {
        row0 = blockIdx.y * BM; row_end = row0 + BM; c = 0;
    }
    int n0 = blockIdx.x * BN;

    extern __shared__ char smem[];
    uint32_t sb = smem_u32(smem);
    int tid  = threadIdx.x;
    int lane = tid & 31;
    int wid  = tid >> 5;
    int wm = (wid >> 1) * 32;   // warp m offset (4 warps in m)
    int wn = (wid & 1) * 64;    // warp n offset (2 warps in n)

    const __nv_bfloat16* Wch = Whi + (size_t)c * wstride;
    const __nv_bfloat16* Wcl = Wlo + (size_t)c * wstride;

    float acc[2][8][4];
    #pragma unroll
    for (int a = 0; a < 2; a++)
        #pragma unroll
        for (int b = 0; b < 8; b++)
            #pragma unroll
            for (int d = 0; d < 4; d++) acc[a][b][d] = 0.f;

    int nk = K / KC;

    auto issue = [&](int i) {
        uint32_t base = sb + (uint32_t)(i & 1) * STAGE;
        int k0 = i * KC;
        #pragma unroll
        for (int it = 0; it < 2; it++) {
            int chunk = tid + it * NTHR;       // 0..511
            int row = chunk >> 2, c16 = chunk & 3;
            uint32_t soff = (uint32_t)(row * 80 + c16 * 16);
            // A (clamp row for partial grouped tiles; garbage rows never stored)
            int gr = row0 + row;
            if (GROUPED && gr >= Bsz) gr = Bsz - 1;
            size_t ga = (size_t)gr * lda + k0 + c16 * 8;
            cp16(base + soff,            Ahi + ga);
            cp16(base + T_SZ + soff,     Alo + ga);
            // B
            size_t gb = (size_t)(n0 + row) * K + k0 + c16 * 8;
            cp16(base + 2 * T_SZ + soff, Wch + gb);
            cp16(base + 3 * T_SZ + soff, Wcl + gb);
        }
        cp_commit();
    };

    issue(0); issue(1);

    int arow = ((lane >> 3) & 1) * 8 + (lane & 7);
    int acol = (lane >> 4) * 16;
    int brow = ((lane >> 4) & 1) * 8 + (lane & 7);
    int bcol = ((lane >> 3) & 1) * 16;

    for (int i = 0; i < nk; i++) {
        if (i == nk - 1) cp_wait<0>(); else cp_wait<1>();
        __syncthreads();
        uint32_t base = sb + (uint32_t)(i & 1) * STAGE;

        #pragma unroll
        for (int kk = 0; kk < 2; kk++) {
            uint32_t ah[2][4], al[2][4], bh[4][4], bl[4][4];
            #pragma unroll
            for (int mt = 0; mt < 2; mt++) {
                uint32_t ra = base + (uint32_t)((wm + mt * 16 + arow) * 80 + kk * 32 + acol);
                ldsm4(ra, ah[mt]);
                ldsm4(ra + T_SZ, al[mt]);
            }
            #pragma unroll
            for (int p = 0; p < 4; p++) {
                uint32_t rb = base + 2 * T_SZ + (uint32_t)((wn + p * 16 + brow) * 80 + kk * 32 + bcol);
                ldsm4(rb, bh[p]);
                ldsm4(rb + T_SZ, bl[p]);
            }
            #pragma unroll
            for (int mt = 0; mt < 2; mt++)
                #pragma unroll
                for (int p = 0; p < 4; p++) {
                    mma16816(acc[mt][2 * p],     ah[mt], &bh[p][0]);
                    mma16816(acc[mt][2 * p],     ah[mt], &bl[p][0]);
                    mma16816(acc[mt][2 * p],     al[mt], &bh[p][0]);
                    mma16816(acc[mt][2 * p + 1], ah[mt], &bh[p][2]);
                    mma16816(acc[mt][2 * p + 1], ah[mt], &bl[p][2]);
                    mma16816(acc[mt][2 * p + 1], al[mt], &bh[p][2]);
                }
        }
        __syncthreads();
        if (i + 2 < nk) issue(i + 2);
    }

    // ---------------- epilogue ----------------
    int gid = lane >> 2, tig = lane & 3;
    const float* bc = bias + c * bstride;

    #pragma unroll
    for (int mt = 0; mt < 2; mt++) {
        int mA = row0 + wm + mt * 16 + gid;
        int mB = mA + 8;
        bool vA = !GROUPED || (mA < row_end);
        bool vB = !GROUPED || (mB < row_end);
        int oA = 0, oB = 0;
        if (EPI == 2) { oA = g_perm[mA]; oB = g_perm[mB]; }

        #pragma unroll
        for (int nt = 0; nt < 8; nt++) {
            int n = n0 + wn + nt * 8 + 2 * tig;
            float* a = acc[mt][nt];
            if (EPI == 0) {
                float b0 = bc[n], b1 = bc[n + 1];
                float v0 = fmaxf(a[0] + b0, 0.f), v1 = fmaxf(a[1] + b1, 0.f);
                float v2 = fmaxf(a[2] + b0, 0.f), v3 = fmaxf(a[3] + b1, 0.f);
                __nv_bfloat16 h0, l0, h1, l1;
                if (vA) {
                    split2(v0, h0, l0); split2(v1, h1, l1);
                    __nv_bfloat162 ph; ph.x = h0; ph.y = h1;
                    __nv_bfloat162 pl; pl.x = l0; pl.y = l1;
                    *reinterpret_cast<__nv_bfloat162*>(Ohi + (size_t)mA * ldo + n) = ph;
                    *reinterpret_cast<__nv_bfloat162*>(Olo + (size_t)mA * ldo + n) = pl;
                }
                if (vB) {
                    split2(v2, h0, l0); split2(v3, h1, l1);
                    __nv_bfloat162 ph; ph.x = h0; ph.y = h1;
                    __nv_bfloat162 pl; pl.x = l0; pl.y = l1;
                    *reinterpret_cast<__nv_bfloat162*>(Ohi + (size_t)mB * ldo + n) = ph;
                    *reinterpret_cast<__nv_bfloat162*>(Olo + (size_t)mB * ldo + n) = pl;
                }
            } else if (EPI == 1) {
                float2 p0; p0.x = a[0]; p0.y = a[1];
                float2 p1; p1.x = a[2]; p1.y = a[3];
                *reinterpret_cast<float2*>(&g_hd[(size_t)mA * 256 + n]) = p0;
                *reinterpret_cast<float2*>(&g_hd[(size_t)mB * 256 + n]) = p1;
            } else {
                float b0 = bc[n], b1 = bc[n + 1];
                float2 p0; p0.x = a[0] + b0; p0.y = a[1] + b1;
                float2 p1; p1.x = a[2] + b0; p1.y = a[3] + b1;
                *reinterpret_cast<float2*>(out + (size_t)oA * DIN + n) = p0;
                *reinterpret_cast<float2*>(out + (size_t)oB * DIN + n) = p1;
            }
        }
    }
}

// ---------------- latent: bias + reparameterize + scatter mu/logvar, split z ----
__global__ void latent_k(const float* __restrict__ bmu, const float* __restrict__ blv,
                         float* __restrict__ out) {
    int idx = blockIdx.x * blockDim.x + threadIdx.x;   // over Bsz*LAT
    if (idx >= Bsz * LAT) return;
    int r = idx >> 7;
    int j = idx & 127;
    float mu = g_hd[(size_t)r * 256 + j] + bmu[j];
    float lv = g_hd[(size_t)r * 256 + 128 + j] + blv[j];
    float z = mu + g_epsp[idx] * expf(0.5f * lv);
    __nv_bfloat16 h, l; split2(z, h, l);
    g_zhi[idx] = h; g_zlo[idx] = l;
    int orow = g_perm[r];
    size_t OFF_MU = (size_t)Bsz * DIN;
    size_t OFF_LV = OFF_MU + (size_t)Bsz * LAT;
    out[OFF_MU + (size_t)orow * LAT + j] = mu;
    out[OFF_LV + (size_t)orow * LAT + j] = lv;
}

// ---------------- launcher ----------------
extern "C" void kernel_launch(void* const* d_in, const int* in_sizes, int n_in,
                              void* d_out, int out_size)
{
    const float* x        = (const float*)d_in[0];
    const int*   labels   = (const int*)  d_in[1];
    const float* eps      = (const float*)d_in[2];
    const float* W_enc0   = (const float*)d_in[3];
    const float* b_enc0   = (const float*)d_in[4];
    const float* W_enc1   = (const float*)d_in[5];
    const float* b_enc1   = (const float*)d_in[6];
    const float* W_mu     = (const float*)d_in[7];
    const float* b_mu     = (const float*)d_in[8];
    const float* W_logvar = (const float*)d_in[9];
    const float* b_logvar = (const float*)d_in[10];
    const float* W_dec0   = (const float*)d_in[11];
    const float* b_dec0   = (const float*)d_in[12];
    const float* W_dec1   = (const float*)d_in[13];
    const float* b_dec1   = (const float*)d_in[14];
    const float* W_out    = (const float*)d_in[15];
    const float* b_out    = (const float*)d_in[16];
    float* out = (float*)d_out;

    __nv_bfloat16 *xhi, *xlo, *h0hi, *h0lo, *h1hi, *h1lo, *zhi, *zlo, *d1hi, *d1lo, *d2hi, *d2lo;
    __nv_bfloat16 *we0h, *we0l, *we1h, *we1l, *whdh, *whdl, *wd0h, *wd0l, *wd1h, *wd1l, *woh, *wol;
    cudaGetSymbolAddress((void**)&xhi, g_xhi);   cudaGetSymbolAddress((void**)&xlo, g_xlo);
    cudaGetSymbolAddress((void**)&h0hi, g_h0hi); cudaGetSymbolAddress((void**)&h0lo, g_h0lo);
    cudaGetSymbolAddress((void**)&h1hi, g_h1hi); cudaGetSymbolAddress((void**)&h1lo, g_h1lo);
    cudaGetSymbolAddress((void**)&zhi, g_zhi);   cudaGetSymbolAddress((void**)&zlo, g_zlo);
    cudaGetSymbolAddress((void**)&d1hi, g_d1hi); cudaGetSymbolAddress((void**)&d1lo, g_d1lo);
    cudaGetSymbolAddress((void**)&d2hi, g_d2hi); cudaGetSymbolAddress((void**)&d2lo, g_d2lo);
    cudaGetSymbolAddress((void**)&we0h, g_we0h); cudaGetSymbolAddress((void**)&we0l, g_we0l);
    cudaGetSymbolAddress((void**)&we1h, g_we1h); cudaGetSymbolAddress((void**)&we1l, g_we1l);
    cudaGetSymbolAddress((void**)&whdh, g_whdh); cudaGetSymbolAddress((void**)&whdl, g_whdl);
    cudaGetSymbolAddress((void**)&wd0h, g_wd0h); cudaGetSymbolAddress((void**)&wd0l, g_wd0l);
    cudaGetSymbolAddress((void**)&wd1h, g_wd1h); cudaGetSymbolAddress((void**)&wd1l, g_wd1l);
    cudaGetSymbolAddress((void**)&woh, g_woh);   cudaGetSymbolAddress((void**)&wol, g_wol);

    cudaFuncSetAttribute(hmma_gemm_k<0, true>,  cudaFuncAttributeMaxDynamicSharedMemorySize, SMEM_BYTES);
    cudaFuncSetAttribute(hmma_gemm_k<0, false>, cudaFuncAttributeMaxDynamicSharedMemorySize, SMEM_BYTES);
    cudaFuncSetAttribute(hmma_gemm_k<1, false>, cudaFuncAttributeMaxDynamicSharedMemorySize, SMEM_BYTES);
    cudaFuncSetAttribute(hmma_gemm_k<2, false>, cudaFuncAttributeMaxDynamicSharedMemorySize, SMEM_BYTES);

    // 1. routing setup
    zero_k<<<1, 32>>>();
    hist_k<<<(Bsz + 255) / 256, 256>>>(labels);
    build_k<<<1, 1>>>();
    scatter_perm_k<<<(Bsz + 255) / 256, 256>>>(labels);
    gatherconv_k<<<Bsz, NTHR>>>(x, eps);

    // 2. weight transpose + split
    tsplit_k<<<dim3(H0 / 32, DIN / 32, NC), dim3(32, 8)>>>(W_enc0, we0h, we0l, DIN, H0);
    tsplit_k<<<dim3(H1 / 32, H0 / 32, 1), dim3(32, 8)>>>(W_enc1, we1h, we1l, H0, H1);
    tsplit_k<<<dim3(LAT / 32, H1 / 32, 1), dim3(32, 8)>>>(W_mu, whdh, whdl, H1, LAT);
    tsplit_k<<<dim3(LAT / 32, H1 / 32, 1), dim3(32, 8)>>>(W_logvar, whdh + LAT * H1, whdl + LAT * H1, H1, LAT);
    tsplit_k<<<dim3(H1 / 32, LAT / 32, 1), dim3(32, 8)>>>(W_dec0, wd0h, wd0l, LAT, H1);
    tsplit_k<<<dim3(H0 / 32, H1 / 32, NC), dim3(32, 8)>>>(W_dec1, wd1h, wd1l, H1, H0);
    tsplit_k<<<dim3(DIN / 32, H0 / 32, 1), dim3(32, 8)>>>(W_out, woh, wol, H0, DIN);

    // 3. encoder layer 0 (grouped): h0 = relu(x @ W_enc0[c])
    hmma_gemm_k<0, true><<<dim3(H0 / BN, 72), NTHR, SMEM_BYTES>>>(
        xhi, xlo, DIN, we0h, we0l, (size_t)DIN * H0, b_enc0, H0,
        H0, DIN, h0hi, h0lo, H0, nullptr);

    // 4. encoder layer 1: h1 = relu(h0 @ W_enc1)
    hmma_gemm_k<0, false><<<dim3(H1 / BN, Bsz / BM), NTHR, SMEM_BYTES>>>(
        h0hi, h0lo, H0, we1h, we1l, 0, b_enc1, 0,
        H1, H0, h1hi, h1lo, H1, nullptr);

    // 5. heads: g_hd = h1 @ [W_mu | W_logvar]  (raw, bias added in latent_k)
    hmma_gemm_k<1, false><<<dim3(2, Bsz / BM), NTHR, SMEM_BYTES>>>(
        h1hi, h1lo, H1, whdh, whdl, 0, b_mu, 0,
        256, H1, nullptr, nullptr, 0, nullptr);

    // 6. reparameterize + scatter mu/logvar + split z
    latent_k<<<(Bsz * LAT + 255) / 256, 256>>>(b_mu, b_logvar, out);

    // 7. decoder layer 0: d1 = relu(z @ W_dec0)
    hmma_gemm_k<0, false><<<dim3(H1 / BN, Bsz / BM), NTHR, SMEM_BYTES>>>(
        zhi, zlo, LAT, wd0h, wd0l, 0, b_dec0, 0,
        H1, LAT, d1hi, d1lo, H1, nullptr);

    // 8. decoder layer 1 (grouped): d2 = relu(d1 @ W_dec1[c])
    hmma_gemm_k<0, true><<<dim3(H0 / BN, 72), NTHR, SMEM_BYTES>>>(
        d1hi, d1lo, H1, wd1h, wd1l, (size_t)H1 * H0, b_dec1, H0,
        H0, H1, d2hi, d2lo, H0, nullptr);

    // 9. output layer (scatter rows): recon = d2 @ W_out + b_out
    hmma_gemm_k<2, false><<<dim3(DIN / BN, Bsz / BM), NTHR, SMEM_BYTES>>>(
        d2hi, d2lo, H0, woh, wol, 0, b_out, 0,
        DIN, H0, nullptr, nullptr, 0, out);

    (void)in_sizes; (void)n_in; (void)out_size;
}

// round 6
// speedup vs baseline: 2.4574x; 1.0180x over previous
#include <cuda_runtime.h>
#include <cuda_fp16.h>
#include <cstdint>
#include <math.h>

// ---------------- problem constants ----------------
#define Bsz   8192
#define DIN   2048
#define H0    1024
#define H1    512
#define LAT   128
#define NC    8

#define BM 128
#define BN 128
#define KC 64
#define NTHR 256
#define MAX_TILES 80

// smem: 3 tiles per stage (A, Bhi, Blo), each 128 rows x 144B (128B data + 16B pad)
#define T_ROW  144
#define T_SZ   (128 * T_ROW)       // 18432
#define STAGE  (3 * T_SZ)          // 55296
#define SMEM_BYTES (2 * STAGE)     // 110592

// ---------------- device scratch ----------------
__device__ __align__(16) __half g_xh  [Bsz * DIN];
__device__ __align__(16) float  g_epsp[Bsz * LAT];
__device__ __align__(16) __half g_h0h [Bsz * H0];
__device__ __align__(16) __half g_h1h [Bsz * H1];
__device__ __align__(16) float  g_hd  [Bsz * 256];     // mu|logvar raw (permuted rows)
__device__ __align__(16) __half g_zh  [Bsz * LAT];
__device__ __align__(16) __half g_d1h [Bsz * H1];
__device__ __align__(16) __half g_d2h [Bsz * H0];

// transposed split weights [N, K] per cluster (fp16 hi/lo)
__device__ __align__(16) __half g_we0h[NC * DIN * H0];
__device__ __align__(16) __half g_we0l[NC * DIN * H0];
__device__ __align__(16) __half g_we1h[H0 * H1];
__device__ __align__(16) __half g_we1l[H0 * H1];
__device__ __align__(16) __half g_whdh[256 * H1];      // [mu;logvar] concat rows
__device__ __align__(16) __half g_whdl[256 * H1];
__device__ __align__(16) __half g_wd0h[H1 * LAT];
__device__ __align__(16) __half g_wd0l[H1 * LAT];
__device__ __align__(16) __half g_wd1h[NC * H1 * H0];
__device__ __align__(16) __half g_wd1l[NC * H1 * H0];
__device__ __align__(16) __half g_woh [DIN * H0];
__device__ __align__(16) __half g_wol [DIN * H0];

__device__ int g_cnt[NC];
__device__ int g_fill[NC];
__device__ int g_segoff[NC + 1];
__device__ int g_perm[Bsz];

struct Tile { int row_start; int row_end; int cluster; };
__device__ Tile g_tiles[MAX_TILES];
__device__ int  g_ntiles;

// ---------------- helpers ----------------
__device__ __forceinline__ uint32_t smem_u32(const void* p) {
    return (uint32_t)__cvta_generic_to_shared(p);
}
__device__ __forceinline__ void cp16(uint32_t saddr, const void* gptr) {
    asm volatile("cp.async.cg.shared.global [%0], [%1], 16;"
                 :: "r"(saddr), "l"(__cvta_generic_to_global(gptr)) : "memory");
}
__device__ __forceinline__ void cp_commit() {
    asm volatile("cp.async.commit_group;" ::: "memory");
}
template<int N> __device__ __forceinline__ void cp_wait() {
    asm volatile("cp.async.wait_group %0;" :: "n"(N) : "memory");
}
__device__ __forceinline__ void ldsm4(uint32_t a, uint32_t* r) {
    asm volatile("ldmatrix.sync.aligned.m8n8.x4.shared.b16 {%0,%1,%2,%3}, [%4];"
                 : "=r"(r[0]), "=r"(r[1]), "=r"(r[2]), "=r"(r[3]) : "r"(a));
}
__device__ __forceinline__ void mma16816(float* c, const uint32_t* a, const uint32_t* b) {
    asm volatile("mma.sync.aligned.m16n8k16.row.col.f32.f16.f16.f32 "
                 "{%0,%1,%2,%3}, {%4,%5,%6,%7}, {%8,%9}, {%0,%1,%2,%3};"
                 : "+f"(c[0]), "+f"(c[1]), "+f"(c[2]), "+f"(c[3])
                 : "r"(a[0]), "r"(a[1]), "r"(a[2]), "r"(a[3]), "r"(b[0]), "r"(b[1]));
}
__device__ __forceinline__ void split2h(float v, __half& h, __half& l) {
    h = __float2half(v);
    l = __float2half(v - __half2float(h));
}

// ---------------- setup kernels ----------------
__global__ void zero_k() {
    int i = threadIdx.x;
    if (i < NC) { g_cnt[i] = 0; g_fill[i] = 0; }
}
__global__ void hist_k(const int* __restrict__ labels) {
    int i = blockIdx.x * blockDim.x + threadIdx.x;
    if (i < Bsz) atomicAdd(&g_cnt[labels[i]], 1);
}
__global__ void build_k() {
    int off = 0;
    for (int c = 0; c < NC; c++) { g_segoff[c] = off; off += g_cnt[c]; }
    g_segoff[NC] = off;
    int t = 0;
    for (int c = 0; c < NC; c++) {
        int s = g_segoff[c], e = g_segoff[c + 1];
        for (int r = s; r < e; r += BM) {
            g_tiles[t].row_start = r;
            g_tiles[t].row_end   = min(r + BM, e);
            g_tiles[t].cluster   = c;
            t++;
        }
    }
    g_ntiles = t;
}
__global__ void scatter_perm_k(const int* __restrict__ labels) {
    int i = blockIdx.x * blockDim.x + threadIdx.x;
    if (i < Bsz) {
        int c = labels[i];
        int pos = g_segoff[c] + atomicAdd(&g_fill[c], 1);
        g_perm[pos] = i;
    }
}

// gather x rows to permuted order, convert to fp16; gather eps
__global__ void gatherconv_k(const float* __restrict__ x, const float* __restrict__ eps) {
    int r = blockIdx.x;
    int src = g_perm[r];
    const float4* xs = reinterpret_cast<const float4*>(x + (size_t)src * DIN);
    size_t dbase = (size_t)r * DIN;
    for (int j = threadIdx.x; j < DIN / 4; j += NTHR) {
        float4 v = xs[j];
        __half2* dh = reinterpret_cast<__half2*>(g_xh + dbase + 4 * (size_t)j);
        dh[0] = __floats2half2_rn(v.x, v.y);
        dh[1] = __floats2half2_rn(v.z, v.w);
    }
    if (threadIdx.x < LAT / 4) {
        reinterpret_cast<float4*>(g_epsp + (size_t)r * LAT)[threadIdx.x] =
            reinterpret_cast<const float4*>(eps + (size_t)src * LAT)[threadIdx.x];
    }
}

// transpose + split: W [K,N] fp32 -> Wt_hi/lo [N,K] fp16 (C matrices via blockIdx.z)
__global__ void tsplit_k(const float* __restrict__ W,
                         __half* __restrict__ hi, __half* __restrict__ lo,
                         int K, int N) {
    __shared__ float t[32][33];
    int c = blockIdx.z;
    const float* Wc = W + (size_t)c * K * N;
    __half* hic = hi + (size_t)c * K * N;
    __half* loc = lo + (size_t)c * K * N;
    int n0 = blockIdx.x * 32, k0 = blockIdx.y * 32;
    int tx = threadIdx.x;
    for (int i = threadIdx.y; i < 32; i += 8)
        t[i][tx] = Wc[(size_t)(k0 + i) * N + n0 + tx];
    __syncthreads();
    for (int i = threadIdx.y; i < 32; i += 8) {
        float v = t[tx][i];   // = W[k0+tx][n0+i]
        __half h, l; split2h(v, h, l);
        size_t o = (size_t)(n0 + i) * K + k0 + tx;
        hic[o] = h; loc[o] = l;
    }
}

// ---------------- HMMA fp16 GEMM (A 1-term, W 2-term) ----------------
// C[BM,BN] = A[M,K] @ W[K,N] via Wt[N,K]; 2 mma terms (A*Bh + A*Bl), fp32 accum.
// EPI: 0 = relu + fp16 store; 1 = raw fp32 to g_hd; 2 = +bias, scatter fp32 to out
template<int EPI, bool GROUPED>
__global__ __launch_bounds__(NTHR)
void hmma_gemm_k(const __half* __restrict__ A, int lda,
                 const __half* __restrict__ Whi, const __half* __restrict__ Wlo, size_t wstride,
                 const float* __restrict__ bias, int bstride,
                 int N, int K,
                 __half* __restrict__ O, int ldo,
                 float* __restrict__ out)
{
    int row0, row_end, c;
    if (GROUPED) {
        int t = blockIdx.y;
        if (t >= g_ntiles) return;
        Tile tl = g_tiles[t];
        row0 = tl.row_start; row_end = tl.row_end; c = tl.cluster;
    } else {
        row0 = blockIdx.y * BM; row_end = row0 + BM; c = 0;
    }
    int n0 = blockIdx.x * BN;

    extern __shared__ char smem[];
    uint32_t sb = smem_u32(smem);
    int tid  = threadIdx.x;
    int lane = tid & 31;
    int wid  = tid >> 5;
    int wm = (wid >> 1) * 32;   // 4 warps in m
    int wn = (wid & 1) * 64;    // 2 warps in n

    const __half* Wch = Whi + (size_t)c * wstride;
    const __half* Wcl = Wlo + (size_t)c * wstride;

    float acc[2][8][4];
    #pragma unroll
    for (int a = 0; a < 2; a++)
        #pragma unroll
        for (int b = 0; b < 8; b++)
            #pragma unroll
            for (int d = 0; d < 4; d++) acc[a][b][d] = 0.f;

    int nk = K / KC;

    auto issue = [&](int i) {
        uint32_t base = sb + (uint32_t)(i & 1) * STAGE;
        int k0 = i * KC;
        #pragma unroll
        for (int it = 0; it < 4; it++) {
            int chunk = tid + it * NTHR;       // 0..1023
            int row = chunk >> 3, c16 = chunk & 7;
            uint32_t soff = (uint32_t)(row * T_ROW + c16 * 16);
            int gr = row0 + row;
            if (GROUPED && gr >= Bsz) gr = Bsz - 1;
            size_t ga = (size_t)gr * lda + k0 + c16 * 8;
            cp16(base + soff, A + ga);
            size_t gb = (size_t)(n0 + row) * K + k0 + c16 * 8;
            cp16(base + T_SZ + soff,     Wch + gb);
            cp16(base + 2 * T_SZ + soff, Wcl + gb);
        }
        cp_commit();
    };

    issue(0);
    if (nk > 1) issue(1);

    int arow = ((lane >> 3) & 1) * 8 + (lane & 7);
    int acol = (lane >> 4) * 16;
    int brow = ((lane >> 4) & 1) * 8 + (lane & 7);
    int bcol = ((lane >> 3) & 1) * 16;

    for (int i = 0; i < nk; i++) {
        if (i == nk - 1) cp_wait<0>(); else cp_wait<1>();
        __syncthreads();
        uint32_t base = sb + (uint32_t)(i & 1) * STAGE;

        #pragma unroll
        for (int kk = 0; kk < KC / 16; kk++) {
            uint32_t ah[2][4], bh[4][4], bl[4][4];
            #pragma unroll
            for (int mt = 0; mt < 2; mt++) {
                uint32_t ra = base + (uint32_t)((wm + mt * 16 + arow) * T_ROW + kk * 32 + acol);
                ldsm4(ra, ah[mt]);
            }
            #pragma unroll
            for (int p = 0; p < 4; p++) {
                uint32_t rb = base + T_SZ + (uint32_t)((wn + p * 16 + brow) * T_ROW + kk * 32 + bcol);
                ldsm4(rb, bh[p]);
                ldsm4(rb + T_SZ, bl[p]);
            }
            #pragma unroll
            for (int mt = 0; mt < 2; mt++)
                #pragma unroll
                for (int p = 0; p < 4; p++) {
                    mma16816(acc[mt][2 * p],     ah[mt], &bh[p][0]);
                    mma16816(acc[mt][2 * p + 1], ah[mt], &bh[p][2]);
                    mma16816(acc[mt][2 * p],     ah[mt], &bl[p][0]);
                    mma16816(acc[mt][2 * p + 1], ah[mt], &bl[p][2]);
                }
        }
        __syncthreads();
        if (i + 2 < nk) issue(i + 2);
    }

    // ---------------- epilogue ----------------
    int gid = lane >> 2, tig = lane & 3;
    const float* bc = bias + c * bstride;

    #pragma unroll
    for (int mt = 0; mt < 2; mt++) {
        int mA = row0 + wm + mt * 16 + gid;
        int mB = mA + 8;
        bool vA = !GROUPED || (mA < row_end);
        bool vB = !GROUPED || (mB < row_end);
        int oA = 0, oB = 0;
        if (EPI == 2) { oA = g_perm[mA]; oB = g_perm[mB]; }

        #pragma unroll
        for (int nt = 0; nt < 8; nt++) {
            int n = n0 + wn + nt * 8 + 2 * tig;
            float* a = acc[mt][nt];
            if (EPI == 0) {
                float b0 = bc[n], b1 = bc[n + 1];
                if (vA) {
                    float v0 = fmaxf(a[0] + b0, 0.f), v1 = fmaxf(a[1] + b1, 0.f);
                    *reinterpret_cast<__half2*>(O + (size_t)mA * ldo + n) = __floats2half2_rn(v0, v1);
                }
                if (vB) {
                    float v2 = fmaxf(a[2] + b0, 0.f), v3 = fmaxf(a[3] + b1, 0.f);
                    *reinterpret_cast<__half2*>(O + (size_t)mB * ldo + n) = __floats2half2_rn(v2, v3);
                }
            } else if (EPI == 1) {
                float2 p0; p0.x = a[0]; p0.y = a[1];
                float2 p1; p1.x = a[2]; p1.y = a[3];
                *reinterpret_cast<float2*>(&g_hd[(size_t)mA * 256 + n]) = p0;
                *reinterpret_cast<float2*>(&g_hd[(size_t)mB * 256 + n]) = p1;
            } else {
                float b0 = bc[n], b1 = bc[n + 1];
                float2 p0; p0.x = a[0] + b0; p0.y = a[1] + b1;
                float2 p1; p1.x = a[2] + b0; p1.y = a[3] + b1;
                *reinterpret_cast<float2*>(out + (size_t)oA * DIN + n) = p0;
                *reinterpret_cast<float2*>(out + (size_t)oB * DIN + n) = p1;
            }
        }
    }
}

// ---------------- latent: bias + reparameterize + scatter mu/logvar, z->fp16 ----
__global__ void latent_k(const float* __restrict__ bmu, const float* __restrict__ blv,
                         float* __restrict__ out) {
    int idx = blockIdx.x * blockDim.x + threadIdx.x;   // over Bsz*LAT
    if (idx >= Bsz * LAT) return;
    int r = idx >> 7;
    int j = idx & 127;
    float mu = g_hd[(size_t)r * 256 + j] + bmu[j];
    float lv = g_hd[(size_t)r * 256 + 128 + j] + blv[j];
    float z = mu + g_epsp[idx] * expf(0.5f * lv);
    g_zh[idx] = __float2half(z);
    int orow = g_perm[r];
    size_t OFF_MU = (size_t)Bsz * DIN;
    size_t OFF_LV = OFF_MU + (size_t)Bsz * LAT;
    out[OFF_MU + (size_t)orow * LAT + j] = mu;
    out[OFF_LV + (size_t)orow * LAT + j] = lv;
}

// ---------------- launcher ----------------
extern "C" void kernel_launch(void* const* d_in, const int* in_sizes, int n_in,
                              void* d_out, int out_size)
{
    const float* x        = (const float*)d_in[0];
    const int*   labels   = (const int*)  d_in[1];
    const float* eps      = (const float*)d_in[2];
    const float* W_enc0   = (const float*)d_in[3];
    const float* b_enc0   = (const float*)d_in[4];
    const float* W_enc1   = (const float*)d_in[5];
    const float* b_enc1   = (const float*)d_in[6];
    const float* W_mu     = (const float*)d_in[7];
    const float* b_mu     = (const float*)d_in[8];
    const float* W_logvar = (const float*)d_in[9];
    const float* b_logvar = (const float*)d_in[10];
    const float* W_dec0   = (const float*)d_in[11];
    const float* b_dec0   = (const float*)d_in[12];
    const float* W_dec1   = (const float*)d_in[13];
    const float* b_dec1   = (const float*)d_in[14];
    const float* W_out    = (const float*)d_in[15];
    const float* b_out    = (const float*)d_in[16];
    float* out = (float*)d_out;

    __half *xh, *h0h, *h1h, *zh, *d1h, *d2h;
    __half *we0h, *we0l, *we1h, *we1l, *whdh, *whdl, *wd0h, *wd0l, *wd1h, *wd1l, *woh, *wol;
    cudaGetSymbolAddress((void**)&xh, g_xh);
    cudaGetSymbolAddress((void**)&h0h, g_h0h);
    cudaGetSymbolAddress((void**)&h1h, g_h1h);
    cudaGetSymbolAddress((void**)&zh, g_zh);
    cudaGetSymbolAddress((void**)&d1h, g_d1h);
    cudaGetSymbolAddress((void**)&d2h, g_d2h);
    cudaGetSymbolAddress((void**)&we0h, g_we0h); cudaGetSymbolAddress((void**)&we0l, g_we0l);
    cudaGetSymbolAddress((void**)&we1h, g_we1h); cudaGetSymbolAddress((void**)&we1l, g_we1l);
    cudaGetSymbolAddress((void**)&whdh, g_whdh); cudaGetSymbolAddress((void**)&whdl, g_whdl);
    cudaGetSymbolAddress((void**)&wd0h, g_wd0h); cudaGetSymbolAddress((void**)&wd0l, g_wd0l);
    cudaGetSymbolAddress((void**)&wd1h, g_wd1h); cudaGetSymbolAddress((void**)&wd1l, g_wd1l);
    cudaGetSymbolAddress((void**)&woh, g_woh);   cudaGetSymbolAddress((void**)&wol, g_wol);

    cudaFuncSetAttribute(hmma_gemm_k<0, true>,  cudaFuncAttributeMaxDynamicSharedMemorySize, SMEM_BYTES);
    cudaFuncSetAttribute(hmma_gemm_k<0, false>, cudaFuncAttributeMaxDynamicSharedMemorySize, SMEM_BYTES);
    cudaFuncSetAttribute(hmma_gemm_k<1, false>, cudaFuncAttributeMaxDynamicSharedMemorySize, SMEM_BYTES);
    cudaFuncSetAttribute(hmma_gemm_k<2, false>, cudaFuncAttributeMaxDynamicSharedMemorySize, SMEM_BYTES);

    // 1. routing setup
    zero_k<<<1, 32>>>();
    hist_k<<<(Bsz + 255) / 256, 256>>>(labels);
    build_k<<<1, 1>>>();
    scatter_perm_k<<<(Bsz + 255) / 256, 256>>>(labels);
    gatherconv_k<<<Bsz, NTHR>>>(x, eps);

    // 2. weight transpose + split (fp16 hi/lo)
    tsplit_k<<<dim3(H0 / 32, DIN / 32, NC), dim3(32, 8)>>>(W_enc0, we0h, we0l, DIN, H0);
    tsplit_k<<<dim3(H1 / 32, H0 / 32, 1), dim3(32, 8)>>>(W_enc1, we1h, we1l, H0, H1);
    tsplit_k<<<dim3(LAT / 32, H1 / 32, 1), dim3(32, 8)>>>(W_mu, whdh, whdl, H1, LAT);
    tsplit_k<<<dim3(LAT / 32, H1 / 32, 1), dim3(32, 8)>>>(W_logvar, whdh + LAT * H1, whdl + LAT * H1, H1, LAT);
    tsplit_k<<<dim3(H1 / 32, LAT / 32, 1), dim3(32, 8)>>>(W_dec0, wd0h, wd0l, LAT, H1);
    tsplit_k<<<dim3(H0 / 32, H1 / 32, NC), dim3(32, 8)>>>(W_dec1, wd1h, wd1l, H1, H0);
    tsplit_k<<<dim3(DIN / 32, H0 / 32, 1), dim3(32, 8)>>>(W_out, woh, wol, H0, DIN);

    // 3. encoder layer 0 (grouped): h0 = relu(x @ W_enc0[c])
    hmma_gemm_k<0, true><<<dim3(H0 / BN, 72), NTHR, SMEM_BYTES>>>(
        xh, DIN, we0h, we0l, (size_t)DIN * H0, b_enc0, H0,
        H0, DIN, h0h, H0, nullptr);

    // 4. encoder layer 1: h1 = relu(h0 @ W_enc1)
    hmma_gemm_k<0, false><<<dim3(H1 / BN, Bsz / BM), NTHR, SMEM_BYTES>>>(
        h0h, H0, we1h, we1l, 0, b_enc1, 0,
        H1, H0, h1h, H1, nullptr);

    // 5. heads: g_hd = h1 @ [W_mu | W_logvar]  (raw, bias added in latent_k)
    hmma_gemm_k<1, false><<<dim3(2, Bsz / BM), NTHR, SMEM_BYTES>>>(
        h1h, H1, whdh, whdl, 0, b_mu, 0,
        256, H1, nullptr, 0, nullptr);

    // 6. reparameterize + scatter mu/logvar + z fp16
    latent_k<<<(Bsz * LAT + 255) / 256, 256>>>(b_mu, b_logvar, out);

    // 7. decoder layer 0: d1 = relu(z @ W_dec0)
    hmma_gemm_k<0, false><<<dim3(H1 / BN, Bsz / BM), NTHR, SMEM_BYTES>>>(
        zh, LAT, wd0h, wd0l, 0, b_dec0, 0,
        H1, LAT, d1h, H1, nullptr);

    // 8. decoder layer 1 (grouped): d2 = relu(d1 @ W_dec1[c])
    hmma_gemm_k<0, true><<<dim3(H0 / BN, 72), NTHR, SMEM_BYTES>>>(
        d1h, H1, wd1h, wd1l, (size_t)H1 * H0, b_dec1, H0,
        H0, H1, d2h, H0, nullptr);

    // 9. output layer (scatter rows): recon = d2 @ W_out + b_out
    hmma_gemm_k<2, false><<<dim3(DIN / BN, Bsz / BM), NTHR, SMEM_BYTES>>>(
        d2h, H0, woh, wol, 0, b_out, 0,
        DIN, H0, nullptr, 0, out);

    (void)in_sizes; (void)n_in; (void)out_size;
}

// round 7
// speedup vs baseline: 3.5744x; 1.4545x over previous
#include <cuda_runtime.h>
#include <cuda_fp16.h>
#include <cstdint>
#include <math.h>

// ---------------- problem constants ----------------
#define Bsz   8192
#define DIN   2048
#define H0    1024
#define H1    512
#define LAT   128
#define NC    8

#define BM 256
#define BN 128
#define KC 64
#define NTHR 256
#define MAX_TILES 48

// smem: A tile 256x144B, Bhi/Blo 128x144B each; 2 stages
#define T_ROW  144
#define A_SZ   (BM * T_ROW)            // 36864
#define B_SZ   (BN * T_ROW)            // 18432
#define STAGE  (A_SZ + 2 * B_SZ)       // 73728
#define SMEM_BYTES (2 * STAGE)         // 147456

// ---------------- device scratch ----------------
__device__ __align__(16) __half g_xh  [Bsz * DIN];
__device__ __align__(16) float  g_epsp[Bsz * LAT];
__device__ __align__(16) __half g_h0h [Bsz * H0];
__device__ __align__(16) __half g_h1h [Bsz * H1];
__device__ __align__(16) float  g_hd  [Bsz * 256];     // mu|logvar raw (permuted rows)
__device__ __align__(16) __half g_zh  [Bsz * LAT];
__device__ __align__(16) __half g_d1h [Bsz * H1];
__device__ __align__(16) __half g_d2h [Bsz * H0];

// transposed split weights [N, K] per cluster (fp16 hi/lo)
__device__ __align__(16) __half g_we0h[NC * DIN * H0];
__device__ __align__(16) __half g_we0l[NC * DIN * H0];
__device__ __align__(16) __half g_we1h[H0 * H1];
__device__ __align__(16) __half g_we1l[H0 * H1];
__device__ __align__(16) __half g_whdh[256 * H1];      // [mu;logvar] concat rows
__device__ __align__(16) __half g_whdl[256 * H1];
__device__ __align__(16) __half g_wd0h[H1 * LAT];
__device__ __align__(16) __half g_wd0l[H1 * LAT];
__device__ __align__(16) __half g_wd1h[NC * H1 * H0];
__device__ __align__(16) __half g_wd1l[NC * H1 * H0];
__device__ __align__(16) __half g_woh [DIN * H0];
__device__ __align__(16) __half g_wol [DIN * H0];

__device__ int g_cnt[NC];
__device__ int g_fill[NC];
__device__ int g_segoff[NC + 1];
__device__ int g_perm[Bsz];

struct Tile { int row_start; int row_end; int cluster; };
__device__ Tile g_tiles[MAX_TILES];
__device__ int  g_ntiles;

// ---------------- helpers ----------------
__device__ __forceinline__ uint32_t smem_u32(const void* p) {
    return (uint32_t)__cvta_generic_to_shared(p);
}
__device__ __forceinline__ void cp16(uint32_t saddr, const void* gptr) {
    asm volatile("cp.async.cg.shared.global [%0], [%1], 16;"
                 :: "r"(saddr), "l"(__cvta_generic_to_global(gptr)) : "memory");
}
__device__ __forceinline__ void cp_commit() {
    asm volatile("cp.async.commit_group;" ::: "memory");
}
template<int N> __device__ __forceinline__ void cp_wait() {
    asm volatile("cp.async.wait_group %0;" :: "n"(N) : "memory");
}
__device__ __forceinline__ void ldsm4(uint32_t a, uint32_t* r) {
    asm volatile("ldmatrix.sync.aligned.m8n8.x4.shared.b16 {%0,%1,%2,%3}, [%4];"
                 : "=r"(r[0]), "=r"(r[1]), "=r"(r[2]), "=r"(r[3]) : "r"(a));
}
__device__ __forceinline__ void mma16816(float* c, const uint32_t* a, const uint32_t* b) {
    asm volatile("mma.sync.aligned.m16n8k16.row.col.f32.f16.f16.f32 "
                 "{%0,%1,%2,%3}, {%4,%5,%6,%7}, {%8,%9}, {%0,%1,%2,%3};"
                 : "+f"(c[0]), "+f"(c[1]), "+f"(c[2]), "+f"(c[3])
                 : "r"(a[0]), "r"(a[1]), "r"(a[2]), "r"(a[3]), "r"(b[0]), "r"(b[1]));
}
__device__ __forceinline__ void split2h(float v, __half& h, __half& l) {
    h = __float2half(v);
    l = __float2half(v - __half2float(h));
}

// ---------------- setup kernels ----------------
// fused zero + histogram + prefix + tile table (single block)
__global__ void histbuild_k(const int* __restrict__ labels) {
    __shared__ int scnt[NC];
    int t = threadIdx.x;
    if (t < NC) scnt[t] = 0;
    __syncthreads();
    for (int i = t; i < Bsz; i += NTHR) atomicAdd(&scnt[labels[i]], 1);
    __syncthreads();
    if (t == 0) {
        int off = 0;
        for (int c = 0; c < NC; c++) {
            g_segoff[c] = off; g_cnt[c] = scnt[c]; g_fill[c] = 0; off += scnt[c];
        }
        g_segoff[NC] = off;
        int tt = 0;
        for (int c = 0; c < NC; c++) {
            int s = g_segoff[c], e = g_segoff[c + 1];
            for (int r = s; r < e; r += BM) {
                g_tiles[tt].row_start = r;
                g_tiles[tt].row_end   = min(r + BM, e);
                g_tiles[tt].cluster   = c;
                tt++;
            }
        }
        g_ntiles = tt;
    }
}
__global__ void scatter_perm_k(const int* __restrict__ labels) {
    int i = blockIdx.x * blockDim.x + threadIdx.x;
    if (i < Bsz) {
        int c = labels[i];
        int pos = g_segoff[c] + atomicAdd(&g_fill[c], 1);
        g_perm[pos] = i;
    }
}

// gather x rows to permuted order, convert to fp16; gather eps
__global__ void gatherconv_k(const float* __restrict__ x, const float* __restrict__ eps) {
    int r = blockIdx.x;
    int src = g_perm[r];
    const float4* xs = reinterpret_cast<const float4*>(x + (size_t)src * DIN);
    size_t dbase = (size_t)r * DIN;
    for (int j = threadIdx.x; j < DIN / 4; j += NTHR) {
        float4 v = xs[j];
        __half2* dh = reinterpret_cast<__half2*>(g_xh + dbase + 4 * (size_t)j);
        dh[0] = __floats2half2_rn(v.x, v.y);
        dh[1] = __floats2half2_rn(v.z, v.w);
    }
    if (threadIdx.x < LAT / 4) {
        reinterpret_cast<float4*>(g_epsp + (size_t)r * LAT)[threadIdx.x] =
            reinterpret_cast<const float4*>(eps + (size_t)src * LAT)[threadIdx.x];
    }
}

// transpose + split: W [K,N] fp32 -> Wt_hi/lo [N,K] fp16 (C matrices via blockIdx.z)
__global__ void tsplit_k(const float* __restrict__ W,
                         __half* __restrict__ hi, __half* __restrict__ lo,
                         int K, int N) {
    __shared__ float t[32][33];
    int c = blockIdx.z;
    const float* Wc = W + (size_t)c * K * N;
    __half* hic = hi + (size_t)c * K * N;
    __half* loc = lo + (size_t)c * K * N;
    int n0 = blockIdx.x * 32, k0 = blockIdx.y * 32;
    int tx = threadIdx.x;
    for (int i = threadIdx.y; i < 32; i += 8)
        t[i][tx] = Wc[(size_t)(k0 + i) * N + n0 + tx];
    __syncthreads();
    for (int i = threadIdx.y; i < 32; i += 8) {
        float v = t[tx][i];   // = W[k0+tx][n0+i]
        __half h, l; split2h(v, h, l);
        size_t o = (size_t)(n0 + i) * K + k0 + tx;
        hic[o] = h; loc[o] = l;
    }
}

// ---------------- HMMA fp16 GEMM (A 1-term, W 2-term), CTA 256x128, warp 64x64 ----
// EPI: 0 = relu + fp16 store; 1 = raw fp32 to g_hd; 2 = +bias, scatter fp32 to out
template<int EPI, bool GROUPED>
__global__ __launch_bounds__(NTHR, 1)
void hmma_gemm_k(const __half* __restrict__ A, int lda,
                 const __half* __restrict__ Whi, const __half* __restrict__ Wlo, size_t wstride,
                 const float* __restrict__ bias, int bstride,
                 int N, int K,
                 __half* __restrict__ O, int ldo,
                 float* __restrict__ out)
{
    int row0, row_end, c;
    if (GROUPED) {
        int t = blockIdx.y;
        if (t >= g_ntiles) return;
        Tile tl = g_tiles[t];
        row0 = tl.row_start; row_end = tl.row_end; c = tl.cluster;
    } else {
        row0 = blockIdx.y * BM; row_end = row0 + BM; c = 0;
    }
    int n0 = blockIdx.x * BN;

    extern __shared__ char smem[];
    uint32_t sb = smem_u32(smem);
    int tid  = threadIdx.x;
    int lane = tid & 31;
    int wid  = tid >> 5;
    int wm = (wid >> 1) * 64;   // 4 warps in m (tile 256)
    int wn = (wid & 1) * 64;    // 2 warps in n (tile 128)

    const __half* Wch = Whi + (size_t)c * wstride;
    const __half* Wcl = Wlo + (size_t)c * wstride;

    float acc[4][8][4];
    #pragma unroll
    for (int a = 0; a < 4; a++)
        #pragma unroll
        for (int b = 0; b < 8; b++)
            #pragma unroll
            for (int d = 0; d < 4; d++) acc[a][b][d] = 0.f;

    int nk = K / KC;

    auto issue = [&](int i) {
        uint32_t base = sb + (uint32_t)(i & 1) * STAGE;
        int k0 = i * KC;
        // A: 256 rows x 8 chunks of 16B
        #pragma unroll
        for (int it = 0; it < 8; it++) {
            int chunk = tid + it * NTHR;      // 0..2047
            int row = chunk >> 3, c16 = chunk & 7;
            uint32_t soff = (uint32_t)(row * T_ROW + c16 * 16);
            int gr = row0 + row;
            if (GROUPED && gr >= Bsz) gr = Bsz - 1;
            size_t ga = (size_t)gr * lda + k0 + c16 * 8;
            cp16(base + soff, A + ga);
        }
        // B hi/lo: 128 rows x 8 chunks each
        #pragma unroll
        for (int it = 0; it < 4; it++) {
            int chunk = tid + it * NTHR;      // 0..1023
            int row = chunk >> 3, c16 = chunk & 7;
            uint32_t soff = (uint32_t)(row * T_ROW + c16 * 16);
            size_t gb = (size_t)(n0 + row) * K + k0 + c16 * 8;
            cp16(base + A_SZ + soff,        Wch + gb);
            cp16(base + A_SZ + B_SZ + soff, Wcl + gb);
        }
        cp_commit();
    };

    issue(0);
    if (nk > 1) issue(1);

    int arow = ((lane >> 3) & 1) * 8 + (lane & 7);
    int acol = (lane >> 4) * 16;
    int brow = ((lane >> 4) & 1) * 8 + (lane & 7);
    int bcol = ((lane >> 3) & 1) * 16;

    for (int i = 0; i < nk; i++) {
        if (i == nk - 1) cp_wait<0>(); else cp_wait<1>();
        __syncthreads();
        uint32_t base = sb + (uint32_t)(i & 1) * STAGE;

        #pragma unroll
        for (int kk = 0; kk < KC / 16; kk++) {
            uint32_t ah[4][4], bh[4][4], bl[4][4];
            #pragma unroll
            for (int mt = 0; mt < 4; mt++) {
                uint32_t ra = base + (uint32_t)((wm + mt * 16 + arow) * T_ROW + kk * 32 + acol);
                ldsm4(ra, ah[mt]);
            }
            #pragma unroll
            for (int p = 0; p < 4; p++) {
                uint32_t rb = base + A_SZ + (uint32_t)((wn + p * 16 + brow) * T_ROW + kk * 32 + bcol);
                ldsm4(rb, bh[p]);
                ldsm4(rb + B_SZ, bl[p]);
            }
            #pragma unroll
            for (int mt = 0; mt < 4; mt++)
                #pragma unroll
                for (int p = 0; p < 4; p++) {
                    mma16816(acc[mt][2 * p],     ah[mt], &bh[p][0]);
                    mma16816(acc[mt][2 * p + 1], ah[mt], &bh[p][2]);
                    mma16816(acc[mt][2 * p],     ah[mt], &bl[p][0]);
                    mma16816(acc[mt][2 * p + 1], ah[mt], &bl[p][2]);
                }
        }
        __syncthreads();
        if (i + 2 < nk) issue(i + 2);
    }

    // ---------------- epilogue ----------------
    int gid = lane >> 2, tig = lane & 3;
    const float* bc = bias + c * bstride;

    #pragma unroll
    for (int mt = 0; mt < 4; mt++) {
        int mA = row0 + wm + mt * 16 + gid;
        int mB = mA + 8;
        bool vA = !GROUPED || (mA < row_end);
        bool vB = !GROUPED || (mB < row_end);
        int oA = 0, oB = 0;
        if (EPI == 2) { oA = g_perm[mA]; oB = g_perm[mB]; }

        #pragma unroll
        for (int nt = 0; nt < 8; nt++) {
            int n = n0 + wn + nt * 8 + 2 * tig;
            float* a = acc[mt][nt];
            if (EPI == 0) {
                float b0 = bc[n], b1 = bc[n + 1];
                if (vA) {
                    float v0 = fmaxf(a[0] + b0, 0.f), v1 = fmaxf(a[1] + b1, 0.f);
                    *reinterpret_cast<__half2*>(O + (size_t)mA * ldo + n) = __floats2half2_rn(v0, v1);
                }
                if (vB) {
                    float v2 = fmaxf(a[2] + b0, 0.f), v3 = fmaxf(a[3] + b1, 0.f);
                    *reinterpret_cast<__half2*>(O + (size_t)mB * ldo + n) = __floats2half2_rn(v2, v3);
                }
            } else if (EPI == 1) {
                float2 p0; p0.x = a[0]; p0.y = a[1];
                float2 p1; p1.x = a[2]; p1.y = a[3];
                *reinterpret_cast<float2*>(&g_hd[(size_t)mA * 256 + n]) = p0;
                *reinterpret_cast<float2*>(&g_hd[(size_t)mB * 256 + n]) = p1;
            } else {
                float b0 = bc[n], b1 = bc[n + 1];
                float2 p0; p0.x = a[0] + b0; p0.y = a[1] + b1;
                float2 p1; p1.x = a[2] + b0; p1.y = a[3] + b1;
                *reinterpret_cast<float2*>(out + (size_t)oA * DIN + n) = p0;
                *reinterpret_cast<float2*>(out + (size_t)oB * DIN + n) = p1;
            }
        }
    }
}

// ---------------- latent: bias + reparameterize + scatter mu/logvar, z->fp16 ----
__global__ void latent_k(const float* __restrict__ bmu, const float* __restrict__ blv,
                         float* __restrict__ out) {
    int idx = blockIdx.x * blockDim.x + threadIdx.x;   // over Bsz*LAT
    if (idx >= Bsz * LAT) return;
    int r = idx >> 7;
    int j = idx & 127;
    float mu = g_hd[(size_t)r * 256 + j] + bmu[j];
    float lv = g_hd[(size_t)r * 256 + 128 + j] + blv[j];
    float z = mu + g_epsp[idx] * expf(0.5f * lv);
    g_zh[idx] = __float2half(z);
    int orow = g_perm[r];
    size_t OFF_MU = (size_t)Bsz * DIN;
    size_t OFF_LV = OFF_MU + (size_t)Bsz * LAT;
    out[OFF_MU + (size_t)orow * LAT + j] = mu;
    out[OFF_LV + (size_t)orow * LAT + j] = lv;
}

// ---------------- launcher ----------------
extern "C" void kernel_launch(void* const* d_in, const int* in_sizes, int n_in,
                              void* d_out, int out_size)
{
    const float* x        = (const float*)d_in[0];
    const int*   labels   = (const int*)  d_in[1];
    const float* eps      = (const float*)d_in[2];
    const float* W_enc0   = (const float*)d_in[3];
    const float* b_enc0   = (const float*)d_in[4];
    const float* W_enc1   = (const float*)d_in[5];
    const float* b_enc1   = (const float*)d_in[6];
    const float* W_mu     = (const float*)d_in[7];
    const float* b_mu     = (const float*)d_in[8];
    const float* W_logvar = (const float*)d_in[9];
    const float* b_logvar = (const float*)d_in[10];
    const float* W_dec0   = (const float*)d_in[11];
    const float* b_dec0   = (const float*)d_in[12];
    const float* W_dec1   = (const float*)d_in[13];
    const float* b_dec1   = (const float*)d_in[14];
    const float* W_out    = (const float*)d_in[15];
    const float* b_out    = (const float*)d_in[16];
    float* out = (float*)d_out;

    __half *xh, *h0h, *h1h, *zh, *d1h, *d2h;
    __half *we0h, *we0l, *we1h, *we1l, *whdh, *whdl, *wd0h, *wd0l, *wd1h, *wd1l, *woh, *wol;
    cudaGetSymbolAddress((void**)&xh, g_xh);
    cudaGetSymbolAddress((void**)&h0h, g_h0h);
    cudaGetSymbolAddress((void**)&h1h, g_h1h);
    cudaGetSymbolAddress((void**)&zh, g_zh);
    cudaGetSymbolAddress((void**)&d1h, g_d1h);
    cudaGetSymbolAddress((void**)&d2h, g_d2h);
    cudaGetSymbolAddress((void**)&we0h, g_we0h); cudaGetSymbolAddress((void**)&we0l, g_we0l);
    cudaGetSymbolAddress((void**)&we1h, g_we1h); cudaGetSymbolAddress((void**)&we1l, g_we1l);
    cudaGetSymbolAddress((void**)&whdh, g_whdh); cudaGetSymbolAddress((void**)&whdl, g_whdl);
    cudaGetSymbolAddress((void**)&wd0h, g_wd0h); cudaGetSymbolAddress((void**)&wd0l, g_wd0l);
    cudaGetSymbolAddress((void**)&wd1h, g_wd1h); cudaGetSymbolAddress((void**)&wd1l, g_wd1l);
    cudaGetSymbolAddress((void**)&woh, g_woh);   cudaGetSymbolAddress((void**)&wol, g_wol);

    cudaFuncSetAttribute(hmma_gemm_k<0, true>,  cudaFuncAttributeMaxDynamicSharedMemorySize, SMEM_BYTES);
    cudaFuncSetAttribute(hmma_gemm_k<0, false>, cudaFuncAttributeMaxDynamicSharedMemorySize, SMEM_BYTES);
    cudaFuncSetAttribute(hmma_gemm_k<1, false>, cudaFuncAttributeMaxDynamicSharedMemorySize, SMEM_BYTES);
    cudaFuncSetAttribute(hmma_gemm_k<2, false>, cudaFuncAttributeMaxDynamicSharedMemorySize, SMEM_BYTES);

    // launch order arranged so enc0 GEMM is launch index 5 (ncu -s 5 -c 1 profiles it)
    // 0: split W_enc0 (no deps)
    tsplit_k<<<dim3(H0 / 32, DIN / 32, NC), dim3(32, 8)>>>(W_enc0, we0h, we0l, DIN, H0);
    // 1: split W_dec1
    tsplit_k<<<dim3(H0 / 32, H1 / 32, NC), dim3(32, 8)>>>(W_dec1, wd1h, wd1l, H1, H0);
    // 2: hist + prefix + tile table
    histbuild_k<<<1, NTHR>>>(labels);
    // 3: permutation
    scatter_perm_k<<<(Bsz + 255) / 256, 256>>>(labels);
    // 4: gather + fp16 convert
    gatherconv_k<<<Bsz, NTHR>>>(x, eps);
    // 5: encoder layer 0 (grouped)  <-- PROFILED
    hmma_gemm_k<0, true><<<dim3(H0 / BN, 40), NTHR, SMEM_BYTES>>>(
        xh, DIN, we0h, we0l, (size_t)DIN * H0, b_enc0, H0,
        H0, DIN, h0h, H0, nullptr);

    // remaining weight splits
    tsplit_k<<<dim3(H1 / 32, H0 / 32, 1), dim3(32, 8)>>>(W_enc1, we1h, we1l, H0, H1);
    tsplit_k<<<dim3(LAT / 32, H1 / 32, 1), dim3(32, 8)>>>(W_mu, whdh, whdl, H1, LAT);
    tsplit_k<<<dim3(LAT / 32, H1 / 32, 1), dim3(32, 8)>>>(W_logvar, whdh + LAT * H1, whdl + LAT * H1, H1, LAT);
    tsplit_k<<<dim3(H1 / 32, LAT / 32, 1), dim3(32, 8)>>>(W_dec0, wd0h, wd0l, LAT, H1);
    tsplit_k<<<dim3(DIN / 32, H0 / 32, 1), dim3(32, 8)>>>(W_out, woh, wol, H0, DIN);

    // encoder layer 1: h1 = relu(h0 @ W_enc1)
    hmma_gemm_k<0, false><<<dim3(H1 / BN, Bsz / BM), NTHR, SMEM_BYTES>>>(
        h0h, H0, we1h, we1l, 0, b_enc1, 0,
        H1, H0, h1h, H1, nullptr);

    // heads: g_hd = h1 @ [W_mu | W_logvar]
    hmma_gemm_k<1, false><<<dim3(2, Bsz / BM), NTHR, SMEM_BYTES>>>(
        h1h, H1, whdh, whdl, 0, b_mu, 0,
        256, H1, nullptr, 0, nullptr);

    // reparameterize + scatter mu/logvar + z fp16
    latent_k<<<(Bsz * LAT + 255) / 256, 256>>>(b_mu, b_logvar, out);

    // decoder layer 0: d1 = relu(z @ W_dec0)
    hmma_gemm_k<0, false><<<dim3(H1 / BN, Bsz / BM), NTHR, SMEM_BYTES>>>(
        zh, LAT, wd0h, wd0l, 0, b_dec0, 0,
        H1, LAT, d1h, H1, nullptr);

    // decoder layer 1 (grouped): d2 = relu(d1 @ W_dec1[c])
    hmma_gemm_k<0, true><<<dim3(H0 / BN, 40), NTHR, SMEM_BYTES>>>(
        d1h, H1, wd1h, wd1l, (size_t)H1 * H0, b_dec1, H0,
        H0, H1, d2h, H0, nullptr);

    // output layer (scatter rows): recon = d2 @ W_out + b_out
    hmma_gemm_k<2, false><<<dim3(DIN / BN, Bsz / BM), NTHR, SMEM_BYTES>>>(
        d2h, H0, woh, wol, 0, b_out, 0,
        DIN, H0, nullptr, 0, out);

    (void)in_sizes; (void)n_in; (void)out_size;
}

// round 8
// speedup vs baseline: 3.7207x; 1.0410x over previous
#include <cuda_runtime.h>
#include <cuda_fp16.h>
#include <cstdint>
#include <math.h>

// ---------------- problem constants ----------------
#define Bsz   8192
#define DIN   2048
#define H0    1024
#define H1    512
#define LAT   128
#define NC    8

#define BM 256
#define BN 128
#define KC 64
#define NTHR 256
#define MAX_TILES 48
#define GRID_P 148

// smem: A tile 256x144B, Bhi/Blo 128x144B each; 3 stages
#define T_ROW  144
#define A_SZ   (BM * T_ROW)            // 36864
#define B_SZ   (BN * T_ROW)            // 18432
#define STAGE  (A_SZ + 2 * B_SZ)       // 73728
#define SMEM_BYTES (3 * STAGE)         // 221184

// ---------------- device scratch ----------------
__device__ __align__(16) __half g_xh  [Bsz * DIN];
__device__ __align__(16) float  g_epsp[Bsz * LAT];
__device__ __align__(16) __half g_h0h [Bsz * H0];
__device__ __align__(16) __half g_h1h [Bsz * H1];
__device__ __align__(16) float  g_hd  [Bsz * 256];     // mu|logvar raw (permuted rows)
__device__ __align__(16) __half g_zh  [Bsz * LAT];
__device__ __align__(16) __half g_d1h [Bsz * H1];
__device__ __align__(16) __half g_d2h [Bsz * H0];

// transposed split weights [N, K] per cluster (fp16 hi/lo)
__device__ __align__(16) __half g_we0h[NC * DIN * H0];
__device__ __align__(16) __half g_we0l[NC * DIN * H0];
__device__ __align__(16) __half g_we1h[H0 * H1];
__device__ __align__(16) __half g_we1l[H0 * H1];
__device__ __align__(16) __half g_whdh[256 * H1];      // [mu;logvar] concat rows
__device__ __align__(16) __half g_whdl[256 * H1];
__device__ __align__(16) __half g_wd0h[H1 * LAT];
__device__ __align__(16) __half g_wd0l[H1 * LAT];
__device__ __align__(16) __half g_wd1h[NC * H1 * H0];
__device__ __align__(16) __half g_wd1l[NC * H1 * H0];
__device__ __align__(16) __half g_woh [DIN * H0];
__device__ __align__(16) __half g_wol [DIN * H0];

__device__ int g_segoff[NC + 1];
__device__ int g_fill[NC];
__device__ int g_perm[Bsz];

struct Tile { int row_start; int row_end; int cluster; };
__device__ Tile g_tiles[MAX_TILES];
__device__ int  g_ntiles;

// ---------------- helpers ----------------
__device__ __forceinline__ uint32_t smem_u32(const void* p) {
    return (uint32_t)__cvta_generic_to_shared(p);
}
__device__ __forceinline__ void cp16(uint32_t saddr, const void* gptr) {
    asm volatile("cp.async.cg.shared.global [%0], [%1], 16;"
                 :: "r"(saddr), "l"(__cvta_generic_to_global(gptr)) : "memory");
}
__device__ __forceinline__ void cp_commit() {
    asm volatile("cp.async.commit_group;" ::: "memory");
}
template<int N> __device__ __forceinline__ void cp_wait() {
    asm volatile("cp.async.wait_group %0;" :: "n"(N) : "memory");
}
__device__ __forceinline__ void ldsm4(uint32_t a, uint32_t* r) {
    asm volatile("ldmatrix.sync.aligned.m8n8.x4.shared.b16 {%0,%1,%2,%3}, [%4];"
                 : "=r"(r[0]), "=r"(r[1]), "=r"(r[2]), "=r"(r[3]) : "r"(a));
}
__device__ __forceinline__ void mma16816(float* c, const uint32_t* a, const uint32_t* b) {
    asm volatile("mma.sync.aligned.m16n8k16.row.col.f32.f16.f16.f32 "
                 "{%0,%1,%2,%3}, {%4,%5,%6,%7}, {%8,%9}, {%0,%1,%2,%3};"
                 : "+f"(c[0]), "+f"(c[1]), "+f"(c[2]), "+f"(c[3])
                 : "r"(a[0]), "r"(a[1]), "r"(a[2]), "r"(a[3]), "r"(b[0]), "r"(b[1]));
}
__device__ __forceinline__ void split2h(float v, __half& h, __half& l) {
    h = __float2half(v);
    l = __float2half(v - __half2float(h));
}

// ---------------- setup kernels ----------------
// fused histogram + prefix + tile table (single block)
__global__ void histbuild_k(const int* __restrict__ labels) {
    __shared__ int scnt[NC];
    int t = threadIdx.x;
    if (t < NC) scnt[t] = 0;
    __syncthreads();
    for (int i = t; i < Bsz; i += NTHR) atomicAdd(&scnt[labels[i]], 1);
    __syncthreads();
    if (t == 0) {
        int off = 0;
        for (int c = 0; c < NC; c++) {
            g_segoff[c] = off; g_fill[c] = 0; off += scnt[c];
        }
        g_segoff[NC] = off;
        int tt = 0;
        for (int c = 0; c < NC; c++) {
            int s = g_segoff[c], e = g_segoff[c + 1];
            for (int r = s; r < e; r += BM) {
                g_tiles[tt].row_start = r;
                g_tiles[tt].row_end   = min(r + BM, e);
                g_tiles[tt].cluster   = c;
                tt++;
            }
        }
        g_ntiles = tt;
    }
}

// fused: compute permuted position for source row + gather/convert row
__global__ void scattergather_k(const int* __restrict__ labels,
                                const float* __restrict__ x, const float* __restrict__ eps) {
    __shared__ int spos;
    int r = blockIdx.x;          // source row
    if (threadIdx.x == 0) {
        int c = labels[r];
        int pos = g_segoff[c] + atomicAdd(&g_fill[c], 1);
        g_perm[pos] = r;
        spos = pos;
    }
    __syncthreads();
    int pos = spos;
    const float4* xs = reinterpret_cast<const float4*>(x + (size_t)r * DIN);
    size_t dbase = (size_t)pos * DIN;
    for (int j = threadIdx.x; j < DIN / 4; j += blockDim.x) {
        float4 v = xs[j];
        __half2* dh = reinterpret_cast<__half2*>(g_xh + dbase + 4 * (size_t)j);
        dh[0] = __floats2half2_rn(v.x, v.y);
        dh[1] = __floats2half2_rn(v.z, v.w);
    }
    if (threadIdx.x < LAT / 4) {
        reinterpret_cast<float4*>(g_epsp + (size_t)pos * LAT)[threadIdx.x] =
            reinterpret_cast<const float4*>(eps + (size_t)r * LAT)[threadIdx.x];
    }
}

// transpose + split: W [K,N] fp32 -> Wt_hi/lo [N,K] fp16 (C matrices via blockIdx.z)
__global__ void tsplit_k(const float* __restrict__ W,
                         __half* __restrict__ hi, __half* __restrict__ lo,
                         int K, int N) {
    __shared__ float t[32][33];
    int c = blockIdx.z;
    const float* Wc = W + (size_t)c * K * N;
    __half* hic = hi + (size_t)c * K * N;
    __half* loc = lo + (size_t)c * K * N;
    int n0 = blockIdx.x * 32, k0 = blockIdx.y * 32;
    int tx = threadIdx.x;
    for (int i = threadIdx.y; i < 32; i += 8)
        t[i][tx] = Wc[(size_t)(k0 + i) * N + n0 + tx];
    __syncthreads();
    for (int i = threadIdx.y; i < 32; i += 8) {
        float v = t[tx][i];
        __half h, l; split2h(v, h, l);
        size_t o = (size_t)(n0 + i) * K + k0 + tx;
        hic[o] = h; loc[o] = l;
    }
}

// ---------------- persistent HMMA fp16 GEMM (A 1-term, W 2-term) ----------------
// CTA tile 256x128, warp 64x64, 3-stage cp.async pipeline, 1 sync/iter.
// EPI: 0 = relu + fp16 store; 1 = raw fp32 to g_hd; 2 = +bias, scatter fp32 to out
template<int EPI, bool GROUPED>
__global__ __launch_bounds__(NTHR, 1)
void hmma_gemm_k(const __half* __restrict__ A, int lda,
                 const __half* __restrict__ Whi, const __half* __restrict__ Wlo, size_t wstride,
                 const float* __restrict__ bias, int bstride,
                 int N, int K, int mtiles_in,
                 __half* __restrict__ O, int ldo,
                 float* __restrict__ out)
{
    extern __shared__ char smem[];
    uint32_t sb = smem_u32(smem);
    int tid  = threadIdx.x;
    int lane = tid & 31;
    int wid  = tid >> 5;
    int wm = (wid >> 1) * 64;
    int wn = (wid & 1) * 64;

    int mtiles = GROUPED ? g_ntiles : mtiles_in;
    int ncols  = N / BN;
    int total  = ncols * mtiles;
    int nk = K / KC;

    int arow = ((lane >> 3) & 1) * 8 + (lane & 7);
    int acol = (lane >> 4) * 16;
    int brow = ((lane >> 4) & 1) * 8 + (lane & 7);
    int bcol = ((lane >> 3) & 1) * 16;

    for (int t = blockIdx.x; t < total; t += gridDim.x) {
        int ncol = t / mtiles;
        int mti  = t - ncol * mtiles;
        int row0, row_end, c;
        if (GROUPED) {
            Tile tl = g_tiles[mti];
            row0 = tl.row_start; row_end = tl.row_end; c = tl.cluster;
        } else {
            row0 = mti * BM; row_end = row0 + BM; c = 0;
        }
        int n0 = ncol * BN;

        const __half* Wch = Whi + (size_t)c * wstride;
        const __half* Wcl = Wlo + (size_t)c * wstride;

        float acc[4][8][4];
        #pragma unroll
        for (int a = 0; a < 4; a++)
            #pragma unroll
            for (int b = 0; b < 8; b++)
                #pragma unroll
                for (int d = 0; d < 4; d++) acc[a][b][d] = 0.f;

        auto issue = [&](int i) {
            int st = i % 3;
            uint32_t base = sb + (uint32_t)st * STAGE;
            int k0 = i * KC;
            #pragma unroll
            for (int it = 0; it < 8; it++) {
                int chunk = tid + it * NTHR;
                int row = chunk >> 3, c16 = chunk & 7;
                uint32_t soff = (uint32_t)(row * T_ROW + c16 * 16);
                int gr = row0 + row;
                if (GROUPED && gr >= Bsz) gr = Bsz - 1;
                size_t ga = (size_t)gr * lda + k0 + c16 * 8;
                cp16(base + soff, A + ga);
            }
            #pragma unroll
            for (int it = 0; it < 4; it++) {
                int chunk = tid + it * NTHR;
                int row = chunk >> 3, c16 = chunk & 7;
                uint32_t soff = (uint32_t)(row * T_ROW + c16 * 16);
                size_t gb = (size_t)(n0 + row) * K + k0 + c16 * 8;
                cp16(base + A_SZ + soff,        Wch + gb);
                cp16(base + A_SZ + B_SZ + soff, Wcl + gb);
            }
            cp_commit();
        };

        issue(0);
        if (nk > 1) issue(1);

        for (int i = 0; i < nk; i++) {
            if (i == nk - 1) cp_wait<0>(); else cp_wait<1>();
            __syncthreads();
            if (i + 2 < nk) issue(i + 2);
            uint32_t base = sb + (uint32_t)(i % 3) * STAGE;

            #pragma unroll
            for (int kk = 0; kk < KC / 16; kk++) {
                uint32_t ah[4][4], bh[4][4], bl[4][4];
                #pragma unroll
                for (int mt = 0; mt < 4; mt++) {
                    uint32_t ra = base + (uint32_t)((wm + mt * 16 + arow) * T_ROW + kk * 32 + acol);
                    ldsm4(ra, ah[mt]);
                }
                #pragma unroll
                for (int p = 0; p < 4; p++) {
                    uint32_t rb = base + A_SZ + (uint32_t)((wn + p * 16 + brow) * T_ROW + kk * 32 + bcol);
                    ldsm4(rb, bh[p]);
                    ldsm4(rb + B_SZ, bl[p]);
                }
                #pragma unroll
                for (int mt = 0; mt < 4; mt++)
                    #pragma unroll
                    for (int p = 0; p < 4; p++) {
                        mma16816(acc[mt][2 * p],     ah[mt], &bh[p][0]);
                        mma16816(acc[mt][2 * p + 1], ah[mt], &bh[p][2]);
                        mma16816(acc[mt][2 * p],     ah[mt], &bl[p][0]);
                        mma16816(acc[mt][2 * p + 1], ah[mt], &bl[p][2]);
                    }
            }
            __syncthreads();   // protect stage reuse for next issue
        }

        // ---------------- epilogue ----------------
        int gid = lane >> 2, tig = lane & 3;
        const float* bc = bias + c * bstride;

        #pragma unroll
        for (int mt = 0; mt < 4; mt++) {
            int mA = row0 + wm + mt * 16 + gid;
            int mB = mA + 8;
            bool vA = !GROUPED || (mA < row_end);
            bool vB = !GROUPED || (mB < row_end);
            int oA = 0, oB = 0;
            if (EPI == 2) { oA = g_perm[mA]; oB = g_perm[mB]; }

            #pragma unroll
            for (int nt = 0; nt < 8; nt++) {
                int n = n0 + wn + nt * 8 + 2 * tig;
                float* a = acc[mt][nt];
                if (EPI == 0) {
                    float b0 = bc[n], b1 = bc[n + 1];
                    if (vA) {
                        float v0 = fmaxf(a[0] + b0, 0.f), v1 = fmaxf(a[1] + b1, 0.f);
                        *reinterpret_cast<__half2*>(O + (size_t)mA * ldo + n) = __floats2half2_rn(v0, v1);
                    }
                    if (vB) {
                        float v2 = fmaxf(a[2] + b0, 0.f), v3 = fmaxf(a[3] + b1, 0.f);
                        *reinterpret_cast<__half2*>(O + (size_t)mB * ldo + n) = __floats2half2_rn(v2, v3);
                    }
                } else if (EPI == 1) {
                    float2 p0; p0.x = a[0]; p0.y = a[1];
                    float2 p1; p1.x = a[2]; p1.y = a[3];
                    *reinterpret_cast<float2*>(&g_hd[(size_t)mA * 256 + n]) = p0;
                    *reinterpret_cast<float2*>(&g_hd[(size_t)mB * 256 + n]) = p1;
                } else {
                    float b0 = bc[n], b1 = bc[n + 1];
                    float2 p0; p0.x = a[0] + b0; p0.y = a[1] + b1;
                    float2 p1; p1.x = a[2] + b0; p1.y = a[3] + b1;
                    *reinterpret_cast<float2*>(out + (size_t)oA * DIN + n) = p0;
                    *reinterpret_cast<float2*>(out + (size_t)oB * DIN + n) = p1;
                }
            }
        }
        __syncthreads();   // all warps done with smem before next tile's issue
    }
}

// ---------------- latent: bias + reparameterize + scatter mu/logvar, z->fp16 ----
__global__ void latent_k(const float* __restrict__ bmu, const float* __restrict__ blv,
                         float* __restrict__ out) {
    int idx = blockIdx.x * blockDim.x + threadIdx.x;
    if (idx >= Bsz * LAT) return;
    int r = idx >> 7;
    int j = idx & 127;
    float mu = g_hd[(size_t)r * 256 + j] + bmu[j];
    float lv = g_hd[(size_t)r * 256 + 128 + j] + blv[j];
    float z = mu + g_epsp[idx] * expf(0.5f * lv);
    g_zh[idx] = __float2half(z);
    int orow = g_perm[r];
    size_t OFF_MU = (size_t)Bsz * DIN;
    size_t OFF_LV = OFF_MU + (size_t)Bsz * LAT;
    out[OFF_MU + (size_t)orow * LAT + j] = mu;
    out[OFF_LV + (size_t)orow * LAT + j] = lv;
}

// ---------------- launcher ----------------
extern "C" void kernel_launch(void* const* d_in, const int* in_sizes, int n_in,
                              void* d_out, int out_size)
{
    const float* x        = (const float*)d_in[0];
    const int*   labels   = (const int*)  d_in[1];
    const float* eps      = (const float*)d_in[2];
    const float* W_enc0   = (const float*)d_in[3];
    const float* b_enc0   = (const float*)d_in[4];
    const float* W_enc1   = (const float*)d_in[5];
    const float* b_enc1   = (const float*)d_in[6];
    const float* W_mu     = (const float*)d_in[7];
    const float* b_mu     = (const float*)d_in[8];
    const float* W_logvar = (const float*)d_in[9];
    const float* b_logvar = (const float*)d_in[10];
    const float* W_dec0   = (const float*)d_in[11];
    const float* b_dec0   = (const float*)d_in[12];
    const float* W_dec1   = (const float*)d_in[13];
    const float* b_dec1   = (const float*)d_in[14];
    const float* W_out    = (const float*)d_in[15];
    const float* b_out    = (const float*)d_in[16];
    float* out = (float*)d_out;

    __half *xh, *h0h, *h1h, *zh, *d1h, *d2h;
    __half *we0h, *we0l, *we1h, *we1l, *whdh, *whdl, *wd0h, *wd0l, *wd1h, *wd1l, *woh, *wol;
    cudaGetSymbolAddress((void**)&xh, g_xh);
    cudaGetSymbolAddress((void**)&h0h, g_h0h);
    cudaGetSymbolAddress((void**)&h1h, g_h1h);
    cudaGetSymbolAddress((void**)&zh, g_zh);
    cudaGetSymbolAddress((void**)&d1h, g_d1h);
    cudaGetSymbolAddress((void**)&d2h, g_d2h);
    cudaGetSymbolAddress((void**)&we0h, g_we0h); cudaGetSymbolAddress((void**)&we0l, g_we0l);
    cudaGetSymbolAddress((void**)&we1h, g_we1h); cudaGetSymbolAddress((void**)&we1l, g_we1l);
    cudaGetSymbolAddress((void**)&whdh, g_whdh); cudaGetSymbolAddress((void**)&whdl, g_whdl);
    cudaGetSymbolAddress((void**)&wd0h, g_wd0h); cudaGetSymbolAddress((void**)&wd0l, g_wd0l);
    cudaGetSymbolAddress((void**)&wd1h, g_wd1h); cudaGetSymbolAddress((void**)&wd1l, g_wd1l);
    cudaGetSymbolAddress((void**)&woh, g_woh);   cudaGetSymbolAddress((void**)&wol, g_wol);

    cudaFuncSetAttribute(hmma_gemm_k<0, true>,  cudaFuncAttributeMaxDynamicSharedMemorySize, SMEM_BYTES);
    cudaFuncSetAttribute(hmma_gemm_k<0, false>, cudaFuncAttributeMaxDynamicSharedMemorySize, SMEM_BYTES);
    cudaFuncSetAttribute(hmma_gemm_k<1, false>, cudaFuncAttributeMaxDynamicSharedMemorySize, SMEM_BYTES);
    cudaFuncSetAttribute(hmma_gemm_k<2, false>, cudaFuncAttributeMaxDynamicSharedMemorySize, SMEM_BYTES);

    // lazy static stream/events (created on uncaptured correctness call)
    static cudaStream_t s2 = nullptr;
    static cudaEvent_t ev_start = nullptr, ev_we0 = nullptr, ev_rest = nullptr;
    if (!s2) {
        cudaStreamCreateWithFlags(&s2, cudaStreamNonBlocking);
        cudaEventCreateWithFlags(&ev_start, cudaEventDisableTiming);
        cudaEventCreateWithFlags(&ev_we0,   cudaEventDisableTiming);
        cudaEventCreateWithFlags(&ev_rest,  cudaEventDisableTiming);
    }

    // fork: weight splits on s2, routing/gather on default stream
    cudaEventRecord(ev_start, 0);
    cudaStreamWaitEvent(s2, ev_start, 0);

    tsplit_k<<<dim3(H0 / 32, DIN / 32, NC), dim3(32, 8), 0, s2>>>(W_enc0, we0h, we0l, DIN, H0);
    cudaEventRecord(ev_we0, s2);
    tsplit_k<<<dim3(H0 / 32, H1 / 32, NC), dim3(32, 8), 0, s2>>>(W_dec1, wd1h, wd1l, H1, H0);
    tsplit_k<<<dim3(H1 / 32, H0 / 32, 1), dim3(32, 8), 0, s2>>>(W_enc1, we1h, we1l, H0, H1);
    tsplit_k<<<dim3(LAT / 32, H1 / 32, 1), dim3(32, 8), 0, s2>>>(W_mu, whdh, whdl, H1, LAT);
    tsplit_k<<<dim3(LAT / 32, H1 / 32, 1), dim3(32, 8), 0, s2>>>(W_logvar, whdh + LAT * H1, whdl + LAT * H1, H1, LAT);
    tsplit_k<<<dim3(H1 / 32, LAT / 32, 1), dim3(32, 8), 0, s2>>>(W_dec0, wd0h, wd0l, LAT, H1);
    tsplit_k<<<dim3(DIN / 32, H0 / 32, 1), dim3(32, 8), 0, s2>>>(W_out, woh, wol, H0, DIN);
    cudaEventRecord(ev_rest, s2);

    histbuild_k<<<1, NTHR>>>(labels);
    scattergather_k<<<Bsz, 128>>>(labels, x, eps);

    // encoder layer 0 (grouped) — needs we0 split + gather
    cudaStreamWaitEvent(0, ev_we0, 0);
    hmma_gemm_k<0, true><<<GRID_P, NTHR, SMEM_BYTES>>>(
        xh, DIN, we0h, we0l, (size_t)DIN * H0, b_enc0, H0,
        H0, DIN, 0, h0h, H0, nullptr);

    // join remaining splits
    cudaStreamWaitEvent(0, ev_rest, 0);

    // encoder layer 1
    hmma_gemm_k<0, false><<<GRID_P, NTHR, SMEM_BYTES>>>(
        h0h, H0, we1h, we1l, 0, b_enc1, 0,
        H1, H0, Bsz / BM, h1h, H1, nullptr);

    // heads: g_hd = h1 @ [W_mu | W_logvar]
    hmma_gemm_k<1, false><<<GRID_P, NTHR, SMEM_BYTES>>>(
        h1h, H1, whdh, whdl, 0, b_mu, 0,
        256, H1, Bsz / BM, nullptr, 0, nullptr);

    // reparameterize + scatter mu/logvar + z fp16
    latent_k<<<(Bsz * LAT + 255) / 256, 256>>>(b_mu, b_logvar, out);

    // decoder layer 0
    hmma_gemm_k<0, false><<<GRID_P, NTHR, SMEM_BYTES>>>(
        zh, LAT, wd0h, wd0l, 0, b_dec0, 0,
        H1, LAT, Bsz / BM, d1h, H1, nullptr);

    // decoder layer 1 (grouped)
    hmma_gemm_k<0, true><<<GRID_P, NTHR, SMEM_BYTES>>>(
        d1h, H1, wd1h, wd1l, (size_t)H1 * H0, b_dec1, H0,
        H0, H1, 0, d2h, H0, nullptr);

    // output layer (scatter rows)
    hmma_gemm_k<2, false><<<GRID_P, NTHR, SMEM_BYTES>>>(
        d2h, H0, woh, wol, 0, b_out, 0,
        DIN, H0, Bsz / BM, nullptr, 0, out);

    (void)in_sizes; (void)n_in; (void)out_size;
}

// round 9
// speedup vs baseline: 5.6744x; 1.5251x over previous
#include <cuda_runtime.h>
#include <cuda_fp16.h>
#include <cstdint>
#include <math.h>

// ---------------- problem constants ----------------
#define Bsz   8192
#define DIN   2048
#define H0    1024
#define H1    512
#define LAT   128
#define NC    8

#define BM 256
#define BN 128
#define KC 64
#define NTHR 256
#define MAX_TILES 48
#define GRID_P 148

// smem: A tile 256x144B + B tile 128x144B per stage; 3 stages
#define T_ROW  144
#define A_SZ   (BM * T_ROW)            // 36864
#define B_SZ   (BN * T_ROW)            // 18432
#define STAGE  (A_SZ + B_SZ)           // 55296
#define SMEM_BYTES (3 * STAGE)         // 165888

// ---------------- device scratch ----------------
__device__ __align__(16) __half g_xh  [Bsz * DIN];
__device__ __align__(16) float  g_epsp[Bsz * LAT];
__device__ __align__(16) __half g_h0h [Bsz * H0];
__device__ __align__(16) __half g_h1h [Bsz * H1];
__device__ __align__(16) float  g_hd  [Bsz * 256];     // mu|logvar raw (permuted rows)
__device__ __align__(16) __half g_zh  [Bsz * LAT];
__device__ __align__(16) __half g_d1h [Bsz * H1];
__device__ __align__(16) __half g_d2h [Bsz * H0];

// transposed fp16 weights [N, K] per cluster
__device__ __align__(16) __half g_we0[NC * DIN * H0];
__device__ __align__(16) __half g_we1[H0 * H1];
__device__ __align__(16) __half g_whd[256 * H1];       // [mu;logvar] concat rows
__device__ __align__(16) __half g_wd0[H1 * LAT];
__device__ __align__(16) __half g_wd1[NC * H1 * H0];
__device__ __align__(16) __half g_wo [DIN * H0];

__device__ int g_segoff[NC + 1];
__device__ int g_fill[NC];
__device__ int g_perm[Bsz];

struct Tile { int row_start; int row_end; int cluster; };
__device__ Tile g_tiles[MAX_TILES];
__device__ int  g_ntiles;

// ---------------- helpers ----------------
__device__ __forceinline__ uint32_t smem_u32(const void* p) {
    return (uint32_t)__cvta_generic_to_shared(p);
}
__device__ __forceinline__ void cp16(uint32_t saddr, const void* gptr) {
    asm volatile("cp.async.cg.shared.global [%0], [%1], 16;"
                 :: "r"(saddr), "l"(__cvta_generic_to_global(gptr)) : "memory");
}
__device__ __forceinline__ void cp_commit() {
    asm volatile("cp.async.commit_group;" ::: "memory");
}
template<int N> __device__ __forceinline__ void cp_wait() {
    asm volatile("cp.async.wait_group %0;" :: "n"(N) : "memory");
}
__device__ __forceinline__ void ldsm4(uint32_t a, uint32_t* r) {
    asm volatile("ldmatrix.sync.aligned.m8n8.x4.shared.b16 {%0,%1,%2,%3}, [%4];"
                 : "=r"(r[0]), "=r"(r[1]), "=r"(r[2]), "=r"(r[3]) : "r"(a));
}
__device__ __forceinline__ void mma16816(float* c, const uint32_t* a, const uint32_t* b) {
    asm volatile("mma.sync.aligned.m16n8k16.row.col.f32.f16.f16.f32 "
                 "{%0,%1,%2,%3}, {%4,%5,%6,%7}, {%8,%9}, {%0,%1,%2,%3};"
                 : "+f"(c[0]), "+f"(c[1]), "+f"(c[2]), "+f"(c[3])
                 : "r"(a[0]), "r"(a[1]), "r"(a[2]), "r"(a[3]), "r"(b[0]), "r"(b[1]));
}

// ---------------- setup kernels ----------------
__global__ void histbuild_k(const int* __restrict__ labels) {
    __shared__ int scnt[NC];
    int t = threadIdx.x;
    if (t < NC) scnt[t] = 0;
    __syncthreads();
    for (int i = t; i < Bsz; i += NTHR) atomicAdd(&scnt[labels[i]], 1);
    __syncthreads();
    if (t == 0) {
        int off = 0;
        for (int c = 0; c < NC; c++) {
            g_segoff[c] = off; g_fill[c] = 0; off += scnt[c];
        }
        g_segoff[NC] = off;
        int tt = 0;
        for (int c = 0; c < NC; c++) {
            int s = g_segoff[c], e = g_segoff[c + 1];
            for (int r = s; r < e; r += BM) {
                g_tiles[tt].row_start = r;
                g_tiles[tt].row_end   = min(r + BM, e);
                g_tiles[tt].cluster   = c;
                tt++;
            }
        }
        g_ntiles = tt;
    }
}

// fused: compute permuted position for source row + gather/convert row
__global__ void scattergather_k(const int* __restrict__ labels,
                                const float* __restrict__ x, const float* __restrict__ eps) {
    __shared__ int spos;
    int r = blockIdx.x;
    if (threadIdx.x == 0) {
        int c = labels[r];
        int pos = g_segoff[c] + atomicAdd(&g_fill[c], 1);
        g_perm[pos] = r;
        spos = pos;
    }
    __syncthreads();
    int pos = spos;
    const float4* xs = reinterpret_cast<const float4*>(x + (size_t)r * DIN);
    size_t dbase = (size_t)pos * DIN;
    for (int j = threadIdx.x; j < DIN / 4; j += blockDim.x) {
        float4 v = xs[j];
        __half2* dh = reinterpret_cast<__half2*>(g_xh + dbase + 4 * (size_t)j);
        dh[0] = __floats2half2_rn(v.x, v.y);
        dh[1] = __floats2half2_rn(v.z, v.w);
    }
    if (threadIdx.x < LAT / 4) {
        reinterpret_cast<float4*>(g_epsp + (size_t)pos * LAT)[threadIdx.x] =
            reinterpret_cast<const float4*>(eps + (size_t)r * LAT)[threadIdx.x];
    }
}

// transpose + convert: W [K,N] fp32 -> Wt [N,K] fp16 (C matrices via blockIdx.z)
__global__ void tsplit_k(const float* __restrict__ W,
                         __half* __restrict__ hi,
                         int K, int N) {
    __shared__ float t[32][33];
    int c = blockIdx.z;
    const float* Wc = W + (size_t)c * K * N;
    __half* hic = hi + (size_t)c * K * N;
    int n0 = blockIdx.x * 32, k0 = blockIdx.y * 32;
    int tx = threadIdx.x;
    for (int i = threadIdx.y; i < 32; i += 8)
        t[i][tx] = Wc[(size_t)(k0 + i) * N + n0 + tx];
    __syncthreads();
    for (int i = threadIdx.y; i < 32; i += 8) {
        size_t o = (size_t)(n0 + i) * K + k0 + tx;
        hic[o] = __float2half(t[tx][i]);
    }
}

// ---------------- persistent HMMA fp16 GEMM (single-term) ----------------
// CTA tile 256x128, warp 64x64, 3-stage cp.async pipeline, 1 sync/iter.
// EPI: 0 = relu + fp16 store; 1 = raw fp32 to g_hd; 2 = +bias, scatter fp32 to out
template<int EPI, bool GROUPED>
__global__ __launch_bounds__(NTHR, 1)
void hmma_gemm_k(const __half* __restrict__ A, int lda,
                 const __half* __restrict__ W, size_t wstride,
                 const float* __restrict__ bias, int bstride,
                 int N, int K, int mtiles_in,
                 __half* __restrict__ O, int ldo,
                 float* __restrict__ out)
{
    extern __shared__ char smem[];
    uint32_t sb = smem_u32(smem);
    int tid  = threadIdx.x;
    int lane = tid & 31;
    int wid  = tid >> 5;
    int wm = (wid >> 1) * 64;
    int wn = (wid & 1) * 64;

    int mtiles = GROUPED ? g_ntiles : mtiles_in;
    int ncols  = N / BN;
    int total  = ncols * mtiles;
    int nk = K / KC;

    int arow = ((lane >> 3) & 1) * 8 + (lane & 7);
    int acol = (lane >> 4) * 16;
    int brow = ((lane >> 4) & 1) * 8 + (lane & 7);
    int bcol = ((lane >> 3) & 1) * 16;

    for (int t = blockIdx.x; t < total; t += gridDim.x) {
        int ncol = t / mtiles;
        int mti  = t - ncol * mtiles;
        int row0, row_end, c;
        if (GROUPED) {
            Tile tl = g_tiles[mti];
            row0 = tl.row_start; row_end = tl.row_end; c = tl.cluster;
        } else {
            row0 = mti * BM; row_end = row0 + BM; c = 0;
        }
        int n0 = ncol * BN;

        const __half* Wc = W + (size_t)c * wstride;

        float acc[4][8][4];
        #pragma unroll
        for (int a = 0; a < 4; a++)
            #pragma unroll
            for (int b = 0; b < 8; b++)
                #pragma unroll
                for (int d = 0; d < 4; d++) acc[a][b][d] = 0.f;

        auto issue = [&](int i) {
            int st = i % 3;
            uint32_t base = sb + (uint32_t)st * STAGE;
            int k0 = i * KC;
            // A: 256 rows x 8 chunks of 16B
            #pragma unroll
            for (int it = 0; it < 8; it++) {
                int chunk = tid + it * NTHR;
                int row = chunk >> 3, c16 = chunk & 7;
                uint32_t soff = (uint32_t)(row * T_ROW + c16 * 16);
                int gr = row0 + row;
                if (GROUPED && gr >= Bsz) gr = Bsz - 1;
                size_t ga = (size_t)gr * lda + k0 + c16 * 8;
                cp16(base + soff, A + ga);
            }
            // B: 128 rows x 8 chunks
            #pragma unroll
            for (int it = 0; it < 4; it++) {
                int chunk = tid + it * NTHR;
                int row = chunk >> 3, c16 = chunk & 7;
                uint32_t soff = (uint32_t)(row * T_ROW + c16 * 16);
                size_t gb = (size_t)(n0 + row) * K + k0 + c16 * 8;
                cp16(base + A_SZ + soff, Wc + gb);
            }
            cp_commit();
        };

        issue(0);
        if (nk > 1) issue(1);

        for (int i = 0; i < nk; i++) {
            if (i == nk - 1) cp_wait<0>(); else cp_wait<1>();
            // this barrier also orders: all threads finished compute(i-1)
            // before issue(i+2) overwrites stage (i+2)%3 (last used at i-1)
            __syncthreads();
            if (i + 2 < nk) issue(i + 2);
            uint32_t base = sb + (uint32_t)(i % 3) * STAGE;

            #pragma unroll
            for (int kk = 0; kk < KC / 16; kk++) {
                uint32_t ah[4][4], bh[4][4];
                #pragma unroll
                for (int mt = 0; mt < 4; mt++) {
                    uint32_t ra = base + (uint32_t)((wm + mt * 16 + arow) * T_ROW + kk * 32 + acol);
                    ldsm4(ra, ah[mt]);
                }
                #pragma unroll
                for (int p = 0; p < 4; p++) {
                    uint32_t rb = base + A_SZ + (uint32_t)((wn + p * 16 + brow) * T_ROW + kk * 32 + bcol);
                    ldsm4(rb, bh[p]);
                }
                #pragma unroll
                for (int mt = 0; mt < 4; mt++)
                    #pragma unroll
                    for (int p = 0; p < 4; p++) {
                        mma16816(acc[mt][2 * p],     ah[mt], &bh[p][0]);
                        mma16816(acc[mt][2 * p + 1], ah[mt], &bh[p][2]);
                    }
            }
        }

        // ---------------- epilogue (registers + global only) ----------------
        int gid = lane >> 2, tig = lane & 3;
        const float* bc = bias + c * bstride;

        #pragma unroll
        for (int mt = 0; mt < 4; mt++) {
            int mA = row0 + wm + mt * 16 + gid;
            int mB = mA + 8;
            bool vA = !GROUPED || (mA < row_end);
            bool vB = !GROUPED || (mB < row_end);
            int oA = 0, oB = 0;
            if (EPI == 2) { oA = g_perm[mA]; oB = g_perm[mB]; }

            #pragma unroll
            for (int nt = 0; nt < 8; nt++) {
                int n = n0 + wn + nt * 8 + 2 * tig;
                float* a = acc[mt][nt];
                if (EPI == 0) {
                    float b0 = bc[n], b1 = bc[n + 1];
                    if (vA) {
                        float v0 = fmaxf(a[0] + b0, 0.f), v1 = fmaxf(a[1] + b1, 0.f);
                        *reinterpret_cast<__half2*>(O + (size_t)mA * ldo + n) = __floats2half2_rn(v0, v1);
                    }
                    if (vB) {
                        float v2 = fmaxf(a[2] + b0, 0.f), v3 = fmaxf(a[3] + b1, 0.f);
                        *reinterpret_cast<__half2*>(O + (size_t)mB * ldo + n) = __floats2half2_rn(v2, v3);
                    }
                } else if (EPI == 1) {
                    float2 p0; p0.x = a[0]; p0.y = a[1];
                    float2 p1; p1.x = a[2]; p1.y = a[3];
                    *reinterpret_cast<float2*>(&g_hd[(size_t)mA * 256 + n]) = p0;
                    *reinterpret_cast<float2*>(&g_hd[(size_t)mB * 256 + n]) = p1;
                } else {
                    float b0 = bc[n], b1 = bc[n + 1];
                    float2 p0; p0.x = a[0] + b0; p0.y = a[1] + b1;
                    float2 p1; p1.x = a[2] + b0; p1.y = a[3] + b1;
                    *reinterpret_cast<float2*>(out + (size_t)oA * DIN + n) = p0;
                    *reinterpret_cast<float2*>(out + (size_t)oB * DIN + n) = p1;
                }
            }
        }
        // stage-reuse guard: next tile's issue(0)/issue(1) must not overwrite
        // stages still being computed on by straggler warps
        __syncthreads();
    }
}

// ---------------- latent: bias + reparameterize + scatter mu/logvar, z->fp16 ----
__global__ void latent_k(const float* __restrict__ bmu, const float* __restrict__ blv,
                         float* __restrict__ out) {
    int idx = blockIdx.x * blockDim.x + threadIdx.x;
    if (idx >= Bsz * LAT) return;
    int r = idx >> 7;
    int j = idx & 127;
    float mu = g_hd[(size_t)r * 256 + j] + bmu[j];
    float lv = g_hd[(size_t)r * 256 + 128 + j] + blv[j];
    float z = mu + g_epsp[idx] * expf(0.5f * lv);
    g_zh[idx] = __float2half(z);
    int orow = g_perm[r];
    size_t OFF_MU = (size_t)Bsz * DIN;
    size_t OFF_LV = OFF_MU + (size_t)Bsz * LAT;
    out[OFF_MU + (size_t)orow * LAT + j] = mu;
    out[OFF_LV + (size_t)orow * LAT + j] = lv;
}

// ---------------- launcher ----------------
extern "C" void kernel_launch(void* const* d_in, const int* in_sizes, int n_in,
                              void* d_out, int out_size)
{
    const float* x        = (const float*)d_in[0];
    const int*   labels   = (const int*)  d_in[1];
    const float* eps      = (const float*)d_in[2];
    const float* W_enc0   = (const float*)d_in[3];
    const float* b_enc0   = (const float*)d_in[4];
    const float* W_enc1   = (const float*)d_in[5];
    const float* b_enc1   = (const float*)d_in[6];
    const float* W_mu     = (const float*)d_in[7];
    const float* b_mu     = (const float*)d_in[8];
    const float* W_logvar = (const float*)d_in[9];
    const float* b_logvar = (const float*)d_in[10];
    const float* W_dec0   = (const float*)d_in[11];
    const float* b_dec0   = (const float*)d_in[12];
    const float* W_dec1   = (const float*)d_in[13];
    const float* b_dec1   = (const float*)d_in[14];
    const float* W_out    = (const float*)d_in[15];
    const float* b_out    = (const float*)d_in[16];
    float* out = (float*)d_out;

    __half *xh, *h0h, *h1h, *zh, *d1h, *d2h;
    __half *we0, *we1, *whd, *wd0, *wd1, *wo;
    cudaGetSymbolAddress((void**)&xh, g_xh);
    cudaGetSymbolAddress((void**)&h0h, g_h0h);
    cudaGetSymbolAddress((void**)&h1h, g_h1h);
    cudaGetSymbolAddress((void**)&zh, g_zh);
    cudaGetSymbolAddress((void**)&d1h, g_d1h);
    cudaGetSymbolAddress((void**)&d2h, g_d2h);
    cudaGetSymbolAddress((void**)&we0, g_we0);
    cudaGetSymbolAddress((void**)&we1, g_we1);
    cudaGetSymbolAddress((void**)&whd, g_whd);
    cudaGetSymbolAddress((void**)&wd0, g_wd0);
    cudaGetSymbolAddress((void**)&wd1, g_wd1);
    cudaGetSymbolAddress((void**)&wo, g_wo);

    cudaFuncSetAttribute(hmma_gemm_k<0, true>,  cudaFuncAttributeMaxDynamicSharedMemorySize, SMEM_BYTES);
    cudaFuncSetAttribute(hmma_gemm_k<0, false>, cudaFuncAttributeMaxDynamicSharedMemorySize, SMEM_BYTES);
    cudaFuncSetAttribute(hmma_gemm_k<1, false>, cudaFuncAttributeMaxDynamicSharedMemorySize, SMEM_BYTES);
    cudaFuncSetAttribute(hmma_gemm_k<2, false>, cudaFuncAttributeMaxDynamicSharedMemorySize, SMEM_BYTES);

    // lazy static stream/events (created on uncaptured correctness call)
    static cudaStream_t s2 = nullptr;
    static cudaEvent_t ev_start = nullptr, ev_we0 = nullptr, ev_rest = nullptr;
    if (!s2) {
        cudaStreamCreateWithFlags(&s2, cudaStreamNonBlocking);
        cudaEventCreateWithFlags(&ev_start, cudaEventDisableTiming);
        cudaEventCreateWithFlags(&ev_we0,   cudaEventDisableTiming);
        cudaEventCreateWithFlags(&ev_rest,  cudaEventDisableTiming);
    }

    // fork: weight conversions on s2, routing/gather on default stream
    cudaEventRecord(ev_start, 0);
    cudaStreamWaitEvent(s2, ev_start, 0);

    tsplit_k<<<dim3(H0 / 32, DIN / 32, NC), dim3(32, 8), 0, s2>>>(W_enc0, we0, DIN, H0);
    cudaEventRecord(ev_we0, s2);
    tsplit_k<<<dim3(H0 / 32, H1 / 32, NC), dim3(32, 8), 0, s2>>>(W_dec1, wd1, H1, H0);
    tsplit_k<<<dim3(H1 / 32, H0 / 32, 1), dim3(32, 8), 0, s2>>>(W_enc1, we1, H0, H1);
    tsplit_k<<<dim3(LAT / 32, H1 / 32, 1), dim3(32, 8), 0, s2>>>(W_mu, whd, H1, LAT);
    tsplit_k<<<dim3(LAT / 32, H1 / 32, 1), dim3(32, 8), 0, s2>>>(W_logvar, whd + LAT * H1, H1, LAT);
    tsplit_k<<<dim3(H1 / 32, LAT / 32, 1), dim3(32, 8), 0, s2>>>(W_dec0, wd0, LAT, H1);
    tsplit_k<<<dim3(DIN / 32, H0 / 32, 1), dim3(32, 8), 0, s2>>>(W_out, wo, H0, DIN);
    cudaEventRecord(ev_rest, s2);

    histbuild_k<<<1, NTHR>>>(labels);
    scattergather_k<<<Bsz, 128>>>(labels, x, eps);

    // encoder layer 0 (grouped) — needs we0 + gather
    cudaStreamWaitEvent(0, ev_we0, 0);
    hmma_gemm_k<0, true><<<GRID_P, NTHR, SMEM_BYTES>>>(
        xh, DIN, we0, (size_t)DIN * H0, b_enc0, H0,
        H0, DIN, 0, h0h, H0, nullptr);

    // join remaining conversions
    cudaStreamWaitEvent(0, ev_rest, 0);

    // encoder layer 1
    hmma_gemm_k<0, false><<<GRID_P, NTHR, SMEM_BYTES>>>(
        h0h, H0, we1, 0, b_enc1, 0,
        H1, H0, Bsz / BM, h1h, H1, nullptr);

    // heads: g_hd = h1 @ [W_mu | W_logvar]
    hmma_gemm_k<1, false><<<GRID_P, NTHR, SMEM_BYTES>>>(
        h1h, H1, whd, 0, b_mu, 0,
        256, H1, Bsz / BM, nullptr, 0, nullptr);

    // reparameterize + scatter mu/logvar + z fp16
    latent_k<<<(Bsz * LAT + 255) / 256, 256>>>(b_mu, b_logvar, out);

    // decoder layer 0
    hmma_gemm_k<0, false><<<GRID_P, NTHR, SMEM_BYTES>>>(
        zh, LAT, wd0, 0, b_dec0, 0,
        H1, LAT, Bsz / BM, d1h, H1, nullptr);

    // decoder layer 1 (grouped)
    hmma_gemm_k<0, true><<<GRID_P, NTHR, SMEM_BYTES>>>(
        d1h, H1, wd1, (size_t)H1 * H0, b_dec1, H0,
        H0, H1, 0, d2h, H0, nullptr);

    // output layer (scatter rows)
    hmma_gemm_k<2, false><<<GRID_P, NTHR, SMEM_BYTES>>>(
        d2h, H0, wo, 0, b_out, 0,
        DIN, H0, Bsz / BM, nullptr, 0, out);

    (void)in_sizes; (void)n_in; (void)out_size;
}